// round 2
// baseline (speedup 1.0000x reference)
#include <cuda_runtime.h>
#include <math.h>

#define BB 64
#define LL 512
#define NSTEPS 20
#define TSZ 32
#define NT (LL / TSZ)               // 16
#define NPAIRS (NT * (NT + 1) / 2)  // 136

// Persistent device scratch (no allocations allowed in kernel_launch).
__device__ float    g_Ahat[(size_t)BB * LL * LL];   // 64 MB state
__device__ float    g_Usym[(size_t)BB * LL * LL];   // 64 MB, constant after init (only ti<=tj tiles used)
__device__ unsigned g_Mbits[(size_t)BB * LL * NT];  // 2 MB bitmask
__device__ float    g_rowpart[(size_t)BB * LL * NT];// 2 MB deterministic row partials
__device__ float    g_Lm[BB * LL];
__device__ float    g_c[BB * LL];

// Pack binary mask M (values exactly 0.0/1.0) into bits. One warp per row.
__global__ void mbits_pack(const float* __restrict__ M) {
    int gtid = blockIdx.x * blockDim.x + threadIdx.x;
    int row  = gtid >> 5;
    int lane = gtid & 31;
    if (row >= BB * LL) return;
    const float* rp = M + (size_t)row * LL;
#pragma unroll
    for (int w = 0; w < NT; w++) {
        unsigned bits = __ballot_sync(0xffffffffu, rp[w * 32 + lane] > 0.5f);
        if (lane == 0) g_Mbits[(size_t)row * NT + w] = bits;
    }
}

// One block handles the tile pair (ti,tj) with ti<=tj for one batch b.
// INIT: src=scores; passes A_hat through, computes+stores Usym, emits row partials.
// LAST: writes A2 to out; skips A_hat store and row partials.
template <bool INIT, bool LAST>
__global__ __launch_bounds__(256) void big_step(
    const float* __restrict__ scores_src,  // used only when INIT
    const float* __restrict__ rho,
    const float* __restrict__ s_p,
    const float* __restrict__ alpha_p,
    const float* __restrict__ lra_p,
    int t,
    float* __restrict__ out) {

    const int b = blockIdx.y;
    int p = blockIdx.x;
    int ti = 0;
    { int rem = p; while (rem >= NT - ti) { rem -= NT - ti; ti++; } p = rem; }
    const int tj = ti + p;
    const bool diag = (ti == tj);

    __shared__ float    sAp[TSZ][TSZ + 1];
    __shared__ float    sAt[TSZ][TSZ + 1];   // transpose tile; reused to stage ah2t
    __shared__ float    sUs[TSZ][TSZ + 1];   // Usym tile; reused to stage a2 when LAST
    __shared__ float    sRp[TSZ][TSZ + 1];
    __shared__ float    sRt[TSZ][TSZ + 1];
    __shared__ unsigned sMw[TSZ];
    __shared__ float    sCi[TSZ], sCj[TSZ];
    __shared__ float    sRed[8][TSZ];
    __shared__ float    s_at, s_s;

    const int tid  = threadIdx.x;
    const int lane = tid & 31;
    const int r0   = tid >> 5;

    if (tid == 0) {
        s_at = INIT ? 0.f : (*alpha_p) * powf(*lra_p, (float)t);
        s_s  = INIT ? (*s_p) : 0.f;
    }

    const float* src = INIT ? scores_src : g_Ahat;
    const size_t baseI = ((size_t)b * LL + (size_t)ti * TSZ) * LL + (size_t)tj * TSZ;
    const size_t baseJ = ((size_t)b * LL + (size_t)tj * TSZ) * LL + (size_t)ti * TSZ;

#pragma unroll
    for (int k = 0; k < 4; k++) {
        int r = r0 + 8 * k;
        sAp[r][lane] = src[baseI + (size_t)r * LL + lane];
        if (!diag) sAt[r][lane] = src[baseJ + (size_t)r * LL + lane];
        if (!INIT) sUs[r][lane] = g_Usym[baseI + (size_t)r * LL + lane];
        sRp[r][lane] = rho[(ti * TSZ + r) * LL + tj * TSZ + lane];
        sRt[r][lane] = rho[(tj * TSZ + r) * LL + ti * TSZ + lane];
    }
    if (tid < TSZ) {
        sMw[tid] = g_Mbits[((size_t)b * LL + (size_t)ti * TSZ + tid) * NT + tj];
        if (!INIT) {
            sCi[tid] = g_c[b * LL + ti * TSZ + tid];
            sCj[tid] = g_c[b * LL + tj * TSZ + tid];
        }
    }
    __syncthreads();

    const float at = s_at;
    float ah2p[4], ah2t[4], a2v[4];
#pragma unroll
    for (int k = 0; k < 4; k++) {
        int r = r0 + 8 * k;
        float m   = (float)((sMw[r] >> lane) & 1u);
        float ahp = sAp[r][lane];
        float aht = diag ? sAp[lane][r] : sAt[lane][r];
        float pv, tv;
        if (INIT) {
            float u = 0.5f * (ahp + aht) - s_s;
            g_Usym[baseI + (size_t)r * LL + lane] = u;
            pv = ahp; tv = aht;  // a_t = 0: update is identity (scores in [0,1))
        } else {
            float u    = sUs[r][lane];
            float mult = fmaf(at * m, u - sCi[r] - sCj[lane], 1.f);
            pv = fminf(fmaxf(fabsf(ahp * mult) - sRp[r][lane] * at, 0.f), 1.f);
            tv = fminf(fmaxf(fabsf(aht * mult) - sRt[lane][r] * at, 0.f), 1.f);
        }
        ah2p[k] = pv;
        ah2t[k] = tv;
        a2v[k]  = (pv + tv) * 0.5f * m;  // symmetric A2 value at (i,j) and (j,i)
    }

    __syncthreads();  // done reading sAt / sUs; safe to reuse as staging
    if (!diag) {
#pragma unroll
        for (int k = 0; k < 4; k++) sAt[lane][r0 + 8 * k] = ah2t[k];
    }
    if (LAST) {
#pragma unroll
        for (int k = 0; k < 4; k++) sUs[r0 + 8 * k][lane] = a2v[k];
    }
    __syncthreads();

#pragma unroll
    for (int k = 0; k < 4; k++) {
        int r = r0 + 8 * k;
        if (!LAST) {
            g_Ahat[baseI + (size_t)r * LL + lane] = ah2p[k];
            if (!diag) g_Ahat[baseJ + (size_t)r * LL + lane] = sAt[r][lane];
        } else {
            out[baseI + (size_t)r * LL + lane] = a2v[k];
            if (!diag) out[baseJ + (size_t)r * LL + lane] = sUs[lane][r];
        }
    }

    if (!LAST) {
        // Row partials for rows in the ti tile: warp-reduce a2 over the 32 columns.
#pragma unroll
        for (int k = 0; k < 4; k++) {
            float v = a2v[k];
#pragma unroll
            for (int o = 16; o > 0; o >>= 1) v += __shfl_down_sync(0xffffffffu, v, o);
            if (lane == 0)
                g_rowpart[((size_t)b * LL + (size_t)ti * TSZ + r0 + 8 * k) * NT + tj] = v;
        }
        // Row partials for rows in the tj tile (off-diagonal only; diagonal would double count).
        if (!diag) {
            float tsum = a2v[0] + a2v[1] + a2v[2] + a2v[3];
            sRed[r0][lane] = tsum;
            __syncthreads();
            if (tid < TSZ) {
                float s2 = 0.f;
#pragma unroll
                for (int w = 0; w < 8; w++) s2 += sRed[w][tid];
                g_rowpart[((size_t)b * LL + (size_t)tj * TSZ + tid) * NT + ti] = s2;
            }
        }
    }
}

// Deterministic reduction of the 16 tile partials per row; updates Lm and c.
template <bool INIT>
__global__ void reduce_k(const float* __restrict__ w_p,
                         const float* __restrict__ belt_p,
                         const float* __restrict__ lrb_p,
                         int t) {
    int idx = blockIdx.x * blockDim.x + threadIdx.x;
    if (idx >= BB * LL) return;
    float s = 0.f;
#pragma unroll
    for (int k = 0; k < NT; k++) s += g_rowpart[(size_t)idx * NT + k];
    float rd = s - 1.f;
    float rl = fmaxf(rd, 0.f);
    float lm;
    if (INIT) lm = (*w_p) * rl;
    else      lm = g_Lm[idx] + (*belt_p) * powf(*lrb_p, (float)t) * rl;
    g_Lm[idx] = lm;
    float sg = (rd > 0.f) ? 1.f : ((rd < 0.f) ? -1.f : 0.f);
    g_c[idx] = lm * sg;
}

extern "C" void kernel_launch(void* const* d_in, const int* in_sizes, int n_in,
                              void* d_out, int out_size) {
    const float* scores  = (const float*)d_in[0];
    const float* M       = (const float*)d_in[1];
    const float* s_p     = (const float*)d_in[2];
    const float* w_p     = (const float*)d_in[3];
    const float* rho     = (const float*)d_in[4];
    const float* alpha_p = (const float*)d_in[5];
    const float* belt_p  = (const float*)d_in[6];
    const float* lra_p   = (const float*)d_in[7];
    const float* lrb_p   = (const float*)d_in[8];
    float* out = (float*)d_out;

    (void)in_sizes; (void)n_in; (void)out_size;

    // 1) Pack binary mask (exact) into bitmask.
    mbits_pack<<<(BB * LL * 32 + 255) / 256, 256>>>(M);

    dim3 grid(NPAIRS, BB);

    // 2) Init: A_hat = scores, Usym = (scores+scores^T)/2 - s, row partials of A0.
    big_step<true, false><<<grid, 256>>>(scores, rho, s_p, alpha_p, lra_p, 0, nullptr);
    reduce_k<true><<<(BB * LL) / 256, 256>>>(w_p, belt_p, lrb_p, 0);

    // 3) 20 proximal steps. Last one writes A2 directly to d_out.
    for (int t = 0; t < NSTEPS; t++) {
        if (t == NSTEPS - 1) {
            big_step<false, true><<<grid, 256>>>(nullptr, rho, s_p, alpha_p, lra_p, t, out);
        } else {
            big_step<false, false><<<grid, 256>>>(nullptr, rho, s_p, alpha_p, lra_p, t, nullptr);
            reduce_k<false><<<(BB * LL) / 256, 256>>>(w_p, belt_p, lrb_p, t);
        }
    }
}

// round 4
// speedup vs baseline: 1.2713x; 1.2713x over previous
#include <cuda_runtime.h>
#include <cuda_fp16.h>
#include <math.h>

#define BB 64
#define LL 512
#define NSTEPS 20
#define NT 16
#define NPAIRS 136

// Persistent device scratch (allocations are forbidden in kernel_launch).
__device__ float    g_Ahat[(size_t)BB * LL * LL];      // 64 MB fp32 state
__device__ __half   g_Uh[(size_t)BB * LL * LL];        // 32 MB fp16 Usym (upper tiles used)
__device__ float    g_RhoT[LL * LL];                   // rho transposed (static)
__device__ unsigned g_Mbits[(size_t)BB * LL * NT];     // 2 MB mask bitmap
__device__ float    g_rp[2][(size_t)BB * LL * NT];     // double-buffered row partials
__device__ float    g_Lm[2][BB * LL];                  // double-buffered multipliers

__device__ __forceinline__ void decode_pair(int p, int& ti, int& tj) {
    int a = 0;
    while (p >= NT - a) { p -= NT - a; a++; }
    ti = a; tj = a + p;
}

// ---------------------------------------------------------------------------
// rho transpose (static, once): g_RhoT[a*L+b] = rho[b*L+a]
__global__ __launch_bounds__(256) void rhot_k(const float* __restrict__ rho) {
    __shared__ float s[32][33];
    const int bx = blockIdx.x, by = blockIdx.y;
    const int x = threadIdx.x & 31, y0 = (threadIdx.x >> 5) * 4;
#pragma unroll
    for (int i = 0; i < 4; i++)
        s[y0 + i][x] = rho[(by * 32 + y0 + i) * LL + bx * 32 + x];
    __syncthreads();
#pragma unroll
    for (int i = 0; i < 4; i++)
        g_RhoT[(bx * 32 + y0 + i) * LL + by * 32 + x] = s[x][y0 + i];
}

// ---------------------------------------------------------------------------
// Init: Usym (fp16), mask bitmap, and row-partials of A0 = sym(scores)*M.
// A_hat0 == scores, so no state copy is made: step 0 reads scores directly.
__global__ __launch_bounds__(256) void init_k(const float* __restrict__ scores,
                                              const float* __restrict__ M,
                                              const float* __restrict__ s_p) {
    int ti, tj; decode_pair(blockIdx.x, ti, tj);
    const int  b    = blockIdx.y;
    const bool diag = (ti == tj);
    const int  tid  = threadIdx.x;
    const int  r    = tid >> 3, g = tid & 7, c0 = g * 4;
    const int  warp = tid >> 5, lane = tid & 31;

    __shared__ float sS[32][33];
    __shared__ float sRed[8][32];

    const size_t rowI  = (size_t)(b * LL) + ti * 32 + r;
    const size_t rowJ  = (size_t)(b * LL) + tj * 32 + r;
    const size_t baseI = rowI * LL + tj * 32 + c0;
    const size_t baseJ = rowJ * LL + ti * 32 + c0;

    const float4 scI = *(const float4*)(scores + baseI);
    const float4 scJ = diag ? scI : *(const float4*)(scores + baseJ);
    const float4 mI4 = *(const float4*)(M + baseI);

    sS[r][c0 + 0] = scJ.x; sS[r][c0 + 1] = scJ.y;
    sS[r][c0 + 2] = scJ.z; sS[r][c0 + 3] = scJ.w;

    // Pack mask bits (M is exactly 0.0/1.0).
    unsigned wI = (((mI4.x > 0.5f) ? 1u : 0u) | ((mI4.y > 0.5f) ? 2u : 0u) |
                   ((mI4.z > 0.5f) ? 4u : 0u) | ((mI4.w > 0.5f) ? 8u : 0u)) << c0;
    wI |= __shfl_xor_sync(0xffffffffu, wI, 1, 8);
    wI |= __shfl_xor_sync(0xffffffffu, wI, 2, 8);
    wI |= __shfl_xor_sync(0xffffffffu, wI, 4, 8);
    if (g == 0) g_Mbits[rowI * NT + tj] = wI;
    if (!diag) {
        const float4 mJ4 = *(const float4*)(M + baseJ);
        unsigned wJ = (((mJ4.x > 0.5f) ? 1u : 0u) | ((mJ4.y > 0.5f) ? 2u : 0u) |
                       ((mJ4.z > 0.5f) ? 4u : 0u) | ((mJ4.w > 0.5f) ? 8u : 0u)) << c0;
        wJ |= __shfl_xor_sync(0xffffffffu, wJ, 1, 8);
        wJ |= __shfl_xor_sync(0xffffffffu, wJ, 2, 8);
        wJ |= __shfl_xor_sync(0xffffffffu, wJ, 4, 8);
        if (g == 0) g_Mbits[rowJ * NT + ti] = wJ;
    }

    const float sv = *s_p;
    __syncthreads();

    const float scIv[4] = {scI.x, scI.y, scI.z, scI.w};
    const float mIv[4]  = {mI4.x, mI4.y, mI4.z, mI4.w};
    float a2v[4], uu[4];
#pragma unroll
    for (int k = 0; k < 4; k++) {
        const float avg = 0.5f * (scIv[k] + sS[c0 + k][r]);
        uu[k]  = avg - sv;
        a2v[k] = avg * mIv[k];           // exact fp32 A0 values
    }
    // Store Usym as fp16 (uint2 = 4 halves)
    {
        __half2 h01 = __floats2half2_rn(uu[0], uu[1]);
        __half2 h23 = __floats2half2_rn(uu[2], uu[3]);
        uint2 p; p.x = *(unsigned*)&h01; p.y = *(unsigned*)&h23;
        *(uint2*)(g_Uh + baseI) = p;
    }

    // Row partials of A0 (buffer 1: step 0 reads (0+1)&1 = 1).
    {
        float v = (a2v[0] + a2v[1]) + (a2v[2] + a2v[3]);
        v += __shfl_down_sync(0xffffffffu, v, 4, 8);
        v += __shfl_down_sync(0xffffffffu, v, 2, 8);
        v += __shfl_down_sync(0xffffffffu, v, 1, 8);
        if (g == 0) g_rp[1][rowI * NT + tj] = v;
    }
    if (!diag) {
#pragma unroll
        for (int k = 0; k < 4; k++) {
            float v = a2v[k];
            v += __shfl_xor_sync(0xffffffffu, v, 16);
            v += __shfl_xor_sync(0xffffffffu, v, 8);
            if (lane < 8) sRed[warp][c0 + k] = v;
        }
        __syncthreads();
        if (tid < 32) {
            float s2 = 0.f;
#pragma unroll
            for (int w = 0; w < 8; w++) s2 += sRed[w][tid];
            g_rp[1][((size_t)(b * LL) + tj * 32 + tid) * NT + ti] = s2;
        }
    }
}

// ---------------------------------------------------------------------------
// One proximal step. FIRST reads scores (A_hat0 == scores) and computes Lm0
// from the init row-partials. LAST writes A2 to out and skips state updates.
// Each block recomputes c (and Lm_t) for its 64 rows from the row-partials:
// identical FP ops on identical data in every block -> bit-identical values.
template <bool FIRST, bool LAST>
__global__ __launch_bounds__(256) void step_k(const float* __restrict__ scores,
                                              const float* __restrict__ rho,
                                              const float* __restrict__ w_p,
                                              const float* __restrict__ alpha_p,
                                              const float* __restrict__ belt_p,
                                              const float* __restrict__ lra_p,
                                              const float* __restrict__ lrb_p,
                                              int t,
                                              float* __restrict__ out) {
    int ti, tj; decode_pair(blockIdx.x, ti, tj);
    const int  b    = blockIdx.y;
    const bool diag = (ti == tj);
    const int  tid  = threadIdx.x;
    const int  r    = tid >> 3, g = tid & 7, c0 = g * 4;
    const int  warp = tid >> 5, lane = tid & 31;

    __shared__ float sAt[32][33];     // A_hat J-side, read transposed
    __shared__ float sStage[32][33];  // J-side output staging
    __shared__ float sRed[8][32];
    __shared__ float sC[64];          // c for ti rows [0..31], tj rows [32..63]

    const size_t rowI  = (size_t)(b * LL) + ti * 32 + r;
    const size_t rowJ  = (size_t)(b * LL) + tj * 32 + r;
    const size_t baseI = rowI * LL + tj * 32 + c0;
    const size_t baseJ = rowJ * LL + ti * 32 + c0;

    const float* __restrict__ Asrc = FIRST ? scores : g_Ahat;

    const float4 ahp4 = *(const float4*)(Asrc + baseI);
    const float4 aJ4  = diag ? ahp4 : *(const float4*)(Asrc + baseJ);
    sAt[r][c0 + 0] = aJ4.x; sAt[r][c0 + 1] = aJ4.y;
    sAt[r][c0 + 2] = aJ4.z; sAt[r][c0 + 3] = aJ4.w;

    const uint2  up    = *(const uint2*)(g_Uh + baseI);
    const float4 rhoI4 = *(const float4*)(rho    + (ti * 32 + r) * LL + tj * 32 + c0);
    const float4 rhoJ4 = *(const float4*)(g_RhoT + (ti * 32 + r) * LL + tj * 32 + c0);
    const unsigned mw  = g_Mbits[rowI * NT + tj];

    const float at = (*alpha_p) * powf(*lra_p, (float)t);

    // --- per-row c (and Lm_t) from row-partials, deterministic ---
    {
        const int rl2 = tid >> 2, q = tid & 3;
        const int rowl = (rl2 < 32) ? (ti * 32 + rl2) : (tj * 32 + (rl2 - 32));
        const float* rpr = g_rp[(t + 1) & 1] + ((size_t)(b * LL) + rowl) * NT;
        const float4 p4 = *(const float4*)(rpr + q * 4);
        float v = (p4.x + p4.y) + (p4.z + p4.w);
        v += __shfl_xor_sync(0xffffffffu, v, 1);
        v += __shfl_xor_sync(0xffffffffu, v, 2);
        const float rd   = v - 1.0f;
        const float rpos = fmaxf(rd, 0.f);
        float lm;
        if (FIRST) lm = (*w_p) * rpos;
        else       lm = g_Lm[(t + 1) & 1][b * LL + rowl]
                        + (*belt_p) * powf(*lrb_p, (float)(t - 1)) * rpos;
        if (q == 0) {
            const float sg = (rd > 0.f) ? 1.f : ((rd < 0.f) ? -1.f : 0.f);
            sC[rl2] = lm * sg;
            if (!LAST && diag && rl2 < 32) g_Lm[t & 1][b * LL + rowl] = lm;
        }
    }
    __syncthreads();

    const float ci = sC[r];
    const float ahpv[4] = {ahp4.x, ahp4.y, ahp4.z, ahp4.w};
    const float rIv[4]  = {rhoI4.x, rhoI4.y, rhoI4.z, rhoI4.w};
    const float rJv[4]  = {rhoJ4.x, rhoJ4.y, rhoJ4.z, rhoJ4.w};
    const float2 u01 = __half22float2(*(const __half2*)&up.x);
    const float2 u23 = __half22float2(*(const __half2*)&up.y);
    const float uv[4] = {u01.x, u01.y, u23.x, u23.y};

    float res[4], a2v[4];
#pragma unroll
    for (int k = 0; k < 4; k++) {
        const float m    = (float)((mw >> (c0 + k)) & 1u);
        const float cj   = sC[32 + c0 + k];
        const float mult = fmaf(at * m, uv[k] - ci - cj, 1.f);
        const float pv   = fminf(fmaxf(fabsf(ahpv[k] * mult) - rIv[k] * at, 0.f), 1.f);
        const float aht  = sAt[c0 + k][r];
        const float tv   = fminf(fmaxf(fabsf(aht * mult) - rJv[k] * at, 0.f), 1.f);
        const float a2   = (pv + tv) * 0.5f * m;
        a2v[k] = a2;
        res[k] = LAST ? a2 : pv;
        sStage[c0 + k][r] = LAST ? a2 : tv;
    }

    // I-side store (coalesced float4)
    {
        float4 o = make_float4(res[0], res[1], res[2], res[3]);
        if (LAST) *(float4*)(out + baseI)    = o;
        else      *(float4*)(g_Ahat + baseI) = o;
    }

    if (!LAST) {
        // Row partials of A2, ti rows
        float v = (a2v[0] + a2v[1]) + (a2v[2] + a2v[3]);
        v += __shfl_down_sync(0xffffffffu, v, 4, 8);
        v += __shfl_down_sync(0xffffffffu, v, 2, 8);
        v += __shfl_down_sync(0xffffffffu, v, 1, 8);
        if (g == 0) g_rp[t & 1][rowI * NT + tj] = v;
        // tj rows (off-diag only)
        if (!diag) {
#pragma unroll
            for (int k = 0; k < 4; k++) {
                float w2 = a2v[k];
                w2 += __shfl_xor_sync(0xffffffffu, w2, 16);
                w2 += __shfl_xor_sync(0xffffffffu, w2, 8);
                if (lane < 8) sRed[warp][c0 + k] = w2;
            }
        }
    }
    __syncthreads();

    // J-side store from staging (coalesced)
    if (!diag) {
        float4 o = make_float4(sStage[r][c0 + 0], sStage[r][c0 + 1],
                               sStage[r][c0 + 2], sStage[r][c0 + 3]);
        if (LAST) *(float4*)(out + baseJ)    = o;
        else      *(float4*)(g_Ahat + baseJ) = o;
    }
    if (!LAST && !diag && tid < 32) {
        float s2 = 0.f;
#pragma unroll
        for (int w = 0; w < 8; w++) s2 += sRed[w][tid];
        g_rp[t & 1][((size_t)(b * LL) + tj * 32 + tid) * NT + ti] = s2;
    }
}

// ---------------------------------------------------------------------------
extern "C" void kernel_launch(void* const* d_in, const int* in_sizes, int n_in,
                              void* d_out, int out_size) {
    const float* scores  = (const float*)d_in[0];
    const float* M       = (const float*)d_in[1];
    const float* s_p     = (const float*)d_in[2];
    const float* w_p     = (const float*)d_in[3];
    const float* rho     = (const float*)d_in[4];
    const float* alpha_p = (const float*)d_in[5];
    const float* belt_p  = (const float*)d_in[6];
    const float* lra_p   = (const float*)d_in[7];
    const float* lrb_p   = (const float*)d_in[8];
    float* out = (float*)d_out;
    (void)in_sizes; (void)n_in; (void)out_size;

    rhot_k<<<dim3(16, 16), 256>>>(rho);

    dim3 grid(NPAIRS, BB);
    init_k<<<grid, 256>>>(scores, M, s_p);

    step_k<true, false><<<grid, 256>>>(scores, rho, w_p, alpha_p, belt_p,
                                       lra_p, lrb_p, 0, nullptr);
    for (int t = 1; t < NSTEPS - 1; t++)
        step_k<false, false><<<grid, 256>>>(scores, rho, w_p, alpha_p, belt_p,
                                            lra_p, lrb_p, t, nullptr);
    step_k<false, true><<<grid, 256>>>(scores, rho, w_p, alpha_p, belt_p,
                                       lra_p, lrb_p, NSTEPS - 1, out);
}

// round 5
// speedup vs baseline: 1.5172x; 1.1934x over previous
#include <cuda_runtime.h>
#include <cuda_fp16.h>
#include <math.h>

#define BB 64
#define LL 512
#define NSTEPS 20
#define NT 16
#define NPAIRS 136

// Persistent device scratch (allocations are forbidden in kernel_launch).
__device__ float    g_Ahat[(size_t)BB * LL * LL];      // 64 MB fp32 state
__device__ __half   g_Uh[(size_t)BB * LL * LL];        // 32 MB fp16 Usym (upper tiles used)
__device__ float    g_RhoT[LL * LL];                   // rho transposed (static)
__device__ unsigned g_Mbits[(size_t)BB * LL * NT];     // 2 MB mask bitmap
__device__ float    g_rp[2][(size_t)BB * LL * NT];     // double-buffered row partials
__device__ float    g_Lm[2][BB * LL];                  // double-buffered multipliers
__device__ float    g_at[NSTEPS];                      // alpha * lr_alpha^t
__device__ float    g_bt[NSTEPS];                      // belt  * lr_belt^t
__device__ uchar2   g_pairs[NPAIRS];                   // (ti, tj) per linear pair id

// ---------------------------------------------------------------------------
// One-time: step coefficients (kills per-thread powf in step_k) + pair table.
__global__ void coef_k(const float* __restrict__ alpha_p,
                       const float* __restrict__ belt_p,
                       const float* __restrict__ lra_p,
                       const float* __restrict__ lrb_p) {
    const int t = threadIdx.x;
    if (t < NSTEPS) {
        g_at[t] = (*alpha_p) * powf(*lra_p, (float)t);
        g_bt[t] = (*belt_p)  * powf(*lrb_p, (float)t);
    }
    if (t < NPAIRS) {
        int p = t, a = 0;
        while (p >= NT - a) { p -= NT - a; a++; }
        g_pairs[t] = make_uchar2((unsigned char)a, (unsigned char)(a + p));
    }
}

// ---------------------------------------------------------------------------
// rho transpose (static, once): g_RhoT[a*L+b] = rho[b*L+a]
__global__ __launch_bounds__(256) void rhot_k(const float* __restrict__ rho) {
    __shared__ float s[32][33];
    const int bx = blockIdx.x, by = blockIdx.y;
    const int x = threadIdx.x & 31, y0 = (threadIdx.x >> 5) * 4;
#pragma unroll
    for (int i = 0; i < 4; i++)
        s[y0 + i][x] = rho[(by * 32 + y0 + i) * LL + bx * 32 + x];
    __syncthreads();
#pragma unroll
    for (int i = 0; i < 4; i++)
        g_RhoT[(bx * 32 + y0 + i) * LL + by * 32 + x] = s[x][y0 + i];
}

// ---------------------------------------------------------------------------
// Init: Usym (fp16), mask bitmap, and row-partials of A0 = sym(scores)*M.
// A_hat0 == scores, so no state copy is made: step 0 reads scores directly.
__global__ __launch_bounds__(256) void init_k(const float* __restrict__ scores,
                                              const float* __restrict__ M,
                                              const float* __restrict__ s_p) {
    const uchar2 pr = g_pairs[blockIdx.x];
    const int ti = pr.x, tj = pr.y;
    const int  b    = blockIdx.y;
    const bool diag = (ti == tj);
    const int  tid  = threadIdx.x;
    const int  r    = tid >> 3, g = tid & 7, c0 = g * 4;
    const int  warp = tid >> 5, lane = tid & 31;

    __shared__ float sS[32][33];
    __shared__ float sRed[8][32];

    const size_t rowI  = (size_t)(b * LL) + ti * 32 + r;
    const size_t rowJ  = (size_t)(b * LL) + tj * 32 + r;
    const size_t baseI = rowI * LL + tj * 32 + c0;
    const size_t baseJ = rowJ * LL + ti * 32 + c0;

    const float4 scI = *(const float4*)(scores + baseI);
    const float4 scJ = diag ? scI : *(const float4*)(scores + baseJ);
    const float4 mI4 = *(const float4*)(M + baseI);

    sS[r][c0 + 0] = scJ.x; sS[r][c0 + 1] = scJ.y;
    sS[r][c0 + 2] = scJ.z; sS[r][c0 + 3] = scJ.w;

    // Pack mask bits (M is exactly 0.0/1.0).
    unsigned wI = (((mI4.x > 0.5f) ? 1u : 0u) | ((mI4.y > 0.5f) ? 2u : 0u) |
                   ((mI4.z > 0.5f) ? 4u : 0u) | ((mI4.w > 0.5f) ? 8u : 0u)) << c0;
    wI |= __shfl_xor_sync(0xffffffffu, wI, 1, 8);
    wI |= __shfl_xor_sync(0xffffffffu, wI, 2, 8);
    wI |= __shfl_xor_sync(0xffffffffu, wI, 4, 8);
    if (g == 0) g_Mbits[rowI * NT + tj] = wI;
    if (!diag) {
        const float4 mJ4 = *(const float4*)(M + baseJ);
        unsigned wJ = (((mJ4.x > 0.5f) ? 1u : 0u) | ((mJ4.y > 0.5f) ? 2u : 0u) |
                       ((mJ4.z > 0.5f) ? 4u : 0u) | ((mJ4.w > 0.5f) ? 8u : 0u)) << c0;
        wJ |= __shfl_xor_sync(0xffffffffu, wJ, 1, 8);
        wJ |= __shfl_xor_sync(0xffffffffu, wJ, 2, 8);
        wJ |= __shfl_xor_sync(0xffffffffu, wJ, 4, 8);
        if (g == 0) g_Mbits[rowJ * NT + ti] = wJ;
    }

    const float sv = *s_p;
    __syncthreads();

    const float scIv[4] = {scI.x, scI.y, scI.z, scI.w};
    const float mIv[4]  = {mI4.x, mI4.y, mI4.z, mI4.w};
    float a2v[4], uu[4];
#pragma unroll
    for (int k = 0; k < 4; k++) {
        const float avg = 0.5f * (scIv[k] + sS[c0 + k][r]);
        uu[k]  = avg - sv;
        a2v[k] = avg * mIv[k];           // exact fp32 A0 values
    }
    // Store Usym as fp16 (uint2 = 4 halves)
    {
        __half2 h01 = __floats2half2_rn(uu[0], uu[1]);
        __half2 h23 = __floats2half2_rn(uu[2], uu[3]);
        uint2 p; p.x = *(unsigned*)&h01; p.y = *(unsigned*)&h23;
        *(uint2*)(g_Uh + baseI) = p;
    }

    // Row partials of A0 (buffer 1: step 0 reads (0+1)&1 = 1).
    {
        float v = (a2v[0] + a2v[1]) + (a2v[2] + a2v[3]);
        v += __shfl_down_sync(0xffffffffu, v, 4, 8);
        v += __shfl_down_sync(0xffffffffu, v, 2, 8);
        v += __shfl_down_sync(0xffffffffu, v, 1, 8);
        if (g == 0) g_rp[1][rowI * NT + tj] = v;
    }
    if (!diag) {
#pragma unroll
        for (int k = 0; k < 4; k++) {
            float v = a2v[k];
            v += __shfl_xor_sync(0xffffffffu, v, 16);
            v += __shfl_xor_sync(0xffffffffu, v, 8);
            if (lane < 8) sRed[warp][c0 + k] = v;
        }
        __syncthreads();
        if (tid < 32) {
            float s2 = 0.f;
#pragma unroll
            for (int w = 0; w < 8; w++) s2 += sRed[w][tid];
            g_rp[1][((size_t)(b * LL) + tj * 32 + tid) * NT + ti] = s2;
        }
    }
}

// ---------------------------------------------------------------------------
// One proximal step. FIRST reads scores (A_hat0 == scores) and computes Lm0
// from the init row-partials. LAST writes A2 to out and skips state updates.
// Each block recomputes c (and Lm_t) for its 64 rows from the row-partials:
// identical FP ops on identical data in every block -> bit-identical values.
template <bool FIRST, bool LAST>
__global__ __launch_bounds__(256) void step_k(const float* __restrict__ scores,
                                              const float* __restrict__ rho,
                                              const float* __restrict__ w_p,
                                              int t,
                                              float* __restrict__ out) {
    const uchar2 pr = g_pairs[blockIdx.x];
    const int ti = pr.x, tj = pr.y;
    const int  b    = blockIdx.y;
    const bool diag = (ti == tj);
    const int  tid  = threadIdx.x;
    const int  r    = tid >> 3, g = tid & 7, c0 = g * 4;
    const int  warp = tid >> 5, lane = tid & 31;

    __shared__ float sAt[32][33];     // A_hat J-side, read transposed
    __shared__ float sStage[32][33];  // J-side output staging
    __shared__ float sRed[8][32];
    __shared__ float sC[64];          // c for ti rows [0..31], tj rows [32..63]

    const size_t rowI  = (size_t)(b * LL) + ti * 32 + r;
    const size_t rowJ  = (size_t)(b * LL) + tj * 32 + r;
    const size_t baseI = rowI * LL + tj * 32 + c0;
    const size_t baseJ = rowJ * LL + ti * 32 + c0;

    const float* __restrict__ Asrc = FIRST ? scores : g_Ahat;

    const float4 ahp4 = *(const float4*)(Asrc + baseI);
    const float4 aJ4  = diag ? ahp4 : *(const float4*)(Asrc + baseJ);
    sAt[r][c0 + 0] = aJ4.x; sAt[r][c0 + 1] = aJ4.y;
    sAt[r][c0 + 2] = aJ4.z; sAt[r][c0 + 3] = aJ4.w;

    const uint2  up    = *(const uint2*)(g_Uh + baseI);
    const float4 rhoI4 = *(const float4*)(rho    + (ti * 32 + r) * LL + tj * 32 + c0);
    const float4 rhoJ4 = *(const float4*)(g_RhoT + (ti * 32 + r) * LL + tj * 32 + c0);
    const unsigned mw  = g_Mbits[rowI * NT + tj];

    const float at = g_at[t];

    // --- per-row c (and Lm_t) from row-partials, deterministic ---
    {
        const int rl2 = tid >> 2, q = tid & 3;
        const int rowl = (rl2 < 32) ? (ti * 32 + rl2) : (tj * 32 + (rl2 - 32));
        const float* rpr = g_rp[(t + 1) & 1] + ((size_t)(b * LL) + rowl) * NT;
        const float4 p4 = *(const float4*)(rpr + q * 4);
        float v = (p4.x + p4.y) + (p4.z + p4.w);
        v += __shfl_xor_sync(0xffffffffu, v, 1);
        v += __shfl_xor_sync(0xffffffffu, v, 2);
        const float rd   = v - 1.0f;
        const float rpos = fmaxf(rd, 0.f);
        float lm;
        if (FIRST) lm = (*w_p) * rpos;
        else       lm = g_Lm[(t + 1) & 1][b * LL + rowl] + g_bt[t - 1] * rpos;
        if (q == 0) {
            const float sg = (rd > 0.f) ? 1.f : ((rd < 0.f) ? -1.f : 0.f);
            sC[rl2] = lm * sg;
            if (!LAST && diag && rl2 < 32) g_Lm[t & 1][b * LL + rowl] = lm;
        }
    }
    __syncthreads();

    const float ci = sC[r];
    const float ahpv[4] = {ahp4.x, ahp4.y, ahp4.z, ahp4.w};
    const float rIv[4]  = {rhoI4.x, rhoI4.y, rhoI4.z, rhoI4.w};
    const float rJv[4]  = {rhoJ4.x, rhoJ4.y, rhoJ4.z, rhoJ4.w};
    const float2 u01 = __half22float2(*(const __half2*)&up.x);
    const float2 u23 = __half22float2(*(const __half2*)&up.y);
    const float uv[4] = {u01.x, u01.y, u23.x, u23.y};

    float res[4], a2v[4];
#pragma unroll
    for (int k = 0; k < 4; k++) {
        const float m    = (float)((mw >> (c0 + k)) & 1u);
        const float cj   = sC[32 + c0 + k];
        const float mult = fmaf(at * m, uv[k] - ci - cj, 1.f);
        const float pv   = fminf(fmaxf(fabsf(ahpv[k] * mult) - rIv[k] * at, 0.f), 1.f);
        const float aht  = sAt[c0 + k][r];
        const float tv   = fminf(fmaxf(fabsf(aht * mult) - rJv[k] * at, 0.f), 1.f);
        const float a2   = (pv + tv) * 0.5f * m;
        a2v[k] = a2;
        res[k] = LAST ? a2 : pv;
        sStage[c0 + k][r] = LAST ? a2 : tv;
    }

    // I-side store (coalesced float4)
    {
        float4 o = make_float4(res[0], res[1], res[2], res[3]);
        if (LAST) *(float4*)(out + baseI)    = o;
        else      *(float4*)(g_Ahat + baseI) = o;
    }

    if (!LAST) {
        // Row partials of A2, ti rows
        float v = (a2v[0] + a2v[1]) + (a2v[2] + a2v[3]);
        v += __shfl_down_sync(0xffffffffu, v, 4, 8);
        v += __shfl_down_sync(0xffffffffu, v, 2, 8);
        v += __shfl_down_sync(0xffffffffu, v, 1, 8);
        if (g == 0) g_rp[t & 1][rowI * NT + tj] = v;
        // tj rows (off-diag only)
        if (!diag) {
#pragma unroll
            for (int k = 0; k < 4; k++) {
                float w2 = a2v[k];
                w2 += __shfl_xor_sync(0xffffffffu, w2, 16);
                w2 += __shfl_xor_sync(0xffffffffu, w2, 8);
                if (lane < 8) sRed[warp][c0 + k] = w2;
            }
        }
    }
    __syncthreads();

    // J-side store from staging (coalesced)
    if (!diag) {
        float4 o = make_float4(sStage[r][c0 + 0], sStage[r][c0 + 1],
                               sStage[r][c0 + 2], sStage[r][c0 + 3]);
        if (LAST) *(float4*)(out + baseJ)    = o;
        else      *(float4*)(g_Ahat + baseJ) = o;
    }
    if (!LAST && !diag && tid < 32) {
        float s2 = 0.f;
#pragma unroll
        for (int w = 0; w < 8; w++) s2 += sRed[w][tid];
        g_rp[t & 1][((size_t)(b * LL) + tj * 32 + tid) * NT + ti] = s2;
    }
}

// ---------------------------------------------------------------------------
extern "C" void kernel_launch(void* const* d_in, const int* in_sizes, int n_in,
                              void* d_out, int out_size) {
    const float* scores  = (const float*)d_in[0];
    const float* M       = (const float*)d_in[1];
    const float* s_p     = (const float*)d_in[2];
    const float* w_p     = (const float*)d_in[3];
    const float* rho     = (const float*)d_in[4];
    const float* alpha_p = (const float*)d_in[5];
    const float* belt_p  = (const float*)d_in[6];
    const float* lra_p   = (const float*)d_in[7];
    const float* lrb_p   = (const float*)d_in[8];
    float* out = (float*)d_out;
    (void)in_sizes; (void)n_in; (void)out_size;

    coef_k<<<1, 256>>>(alpha_p, belt_p, lra_p, lrb_p);
    rhot_k<<<dim3(16, 16), 256>>>(rho);

    dim3 grid(NPAIRS, BB);
    init_k<<<grid, 256>>>(scores, M, s_p);

    step_k<true, false><<<grid, 256>>>(scores, rho, w_p, 0, nullptr);
    for (int t = 1; t < NSTEPS - 1; t++)
        step_k<false, false><<<grid, 256>>>(scores, rho, w_p, t, nullptr);
    step_k<false, true><<<grid, 256>>>(scores, rho, w_p, NSTEPS - 1, out);
}

// round 6
// speedup vs baseline: 1.7278x; 1.1388x over previous
#include <cuda_runtime.h>
#include <cuda_fp16.h>
#include <math.h>

#define BB 64
#define LL 512
#define NSTEPS 20
#define NT 16
#define NPAIRS 136

// Persistent device scratch (allocations are forbidden in kernel_launch).
__device__ float    g_Ahat[(size_t)BB * LL * LL];      // 64 MB fp32 state
__device__ __half   g_Uh[(size_t)BB * LL * LL];        // 32 MB fp16 Usym (upper tiles used)
__device__ __half2  g_RhoP[LL * LL];                   // packed (rho[i,j], rho[j,i]) fp16
__device__ unsigned g_Mbits[(size_t)BB * LL * NT];     // 2 MB mask bitmap
__device__ float    g_rp[2][(size_t)BB * LL * NT];     // double-buffered row partials
__device__ float    g_Lm[2][BB * LL];                  // double-buffered multipliers
__device__ float    g_at[NSTEPS];                      // alpha * lr_alpha^t
__device__ float    g_bt[NSTEPS];                      // belt  * lr_belt^t
__device__ uchar2   g_pairs[NPAIRS];                   // (ti, tj) per linear pair id

// ---------------------------------------------------------------------------
// L2 evict_last cache-policy helpers (pin reused state in L2).
__device__ __forceinline__ unsigned long long mk_pol() {
    unsigned long long p;
    asm("createpolicy.fractional.L2::evict_last.b64 %0, 1.0;" : "=l"(p));
    return p;
}
__device__ __forceinline__ float4 ld_f4_el(const float* a, unsigned long long pol) {
    float4 v;
    asm("ld.global.L2::cache_hint.v4.f32 {%0,%1,%2,%3}, [%4], %5;"
        : "=f"(v.x), "=f"(v.y), "=f"(v.z), "=f"(v.w)
        : "l"(a), "l"(pol));
    return v;
}
__device__ __forceinline__ void st_f4_el(float* a, float4 v, unsigned long long pol) {
    asm volatile("st.global.L2::cache_hint.v4.f32 [%0], {%1,%2,%3,%4}, %5;"
                 :: "l"(a), "f"(v.x), "f"(v.y), "f"(v.z), "f"(v.w), "l"(pol)
                 : "memory");
}
__device__ __forceinline__ uint2 ld_u2_el(const __half* a, unsigned long long pol) {
    uint2 v;
    asm("ld.global.L2::cache_hint.v2.u32 {%0,%1}, [%2], %3;"
        : "=r"(v.x), "=r"(v.y) : "l"(a), "l"(pol));
    return v;
}

// ---------------------------------------------------------------------------
// One-time: step coefficients (kills per-thread powf in step_k) + pair table.
__global__ void coef_k(const float* __restrict__ alpha_p,
                       const float* __restrict__ belt_p,
                       const float* __restrict__ lra_p,
                       const float* __restrict__ lrb_p) {
    const int t = threadIdx.x;
    if (t < NSTEPS) {
        g_at[t] = (*alpha_p) * powf(*lra_p, (float)t);
        g_bt[t] = (*belt_p)  * powf(*lrb_p, (float)t);
    }
    if (t < NPAIRS) {
        int p = t, a = 0;
        while (p >= NT - a) { p -= NT - a; a++; }
        g_pairs[t] = make_uchar2((unsigned char)a, (unsigned char)(a + p));
    }
}

// ---------------------------------------------------------------------------
// Packed rho (static, once): g_RhoP[a*L+b] = (rho[a,b], rho[b,a]) as half2.
__global__ __launch_bounds__(256) void rhop_k(const float* __restrict__ rho) {
    __shared__ float sN[32][33];
    __shared__ float sT[32][33];
    const int bx = blockIdx.x, by = blockIdx.y;
    const int x = threadIdx.x & 31, y0 = (threadIdx.x >> 5) * 4;
#pragma unroll
    for (int i = 0; i < 4; i++) {
        sN[y0 + i][x] = rho[(by * 32 + y0 + i) * LL + bx * 32 + x];
        sT[y0 + i][x] = rho[(bx * 32 + y0 + i) * LL + by * 32 + x];
    }
    __syncthreads();
#pragma unroll
    for (int i = 0; i < 4; i++) {
        const int y = y0 + i;
        g_RhoP[(by * 32 + y) * LL + bx * 32 + x] =
            __floats2half2_rn(sN[y][x], sT[x][y]);
    }
}

// ---------------------------------------------------------------------------
// Init: Usym (fp16), mask bitmap, and row-partials of A0 = sym(scores)*M.
// A_hat0 == scores, so no state copy is made: step 0 reads scores directly.
__global__ __launch_bounds__(256) void init_k(const float* __restrict__ scores,
                                              const float* __restrict__ M,
                                              const float* __restrict__ s_p) {
    const uchar2 pr = g_pairs[blockIdx.x];
    const int ti = pr.x, tj = pr.y;
    const int  b    = blockIdx.y;
    const bool diag = (ti == tj);
    const int  tid  = threadIdx.x;
    const int  r    = tid >> 3, g = tid & 7, c0 = g * 4;
    const int  warp = tid >> 5, lane = tid & 31;

    __shared__ float sS[32][33];
    __shared__ float sRed[8][32];

    const size_t rowI  = (size_t)(b * LL) + ti * 32 + r;
    const size_t rowJ  = (size_t)(b * LL) + tj * 32 + r;
    const size_t baseI = rowI * LL + tj * 32 + c0;
    const size_t baseJ = rowJ * LL + ti * 32 + c0;

    const float4 scI = *(const float4*)(scores + baseI);
    const float4 scJ = diag ? scI : *(const float4*)(scores + baseJ);
    const float4 mI4 = *(const float4*)(M + baseI);

    sS[r][c0 + 0] = scJ.x; sS[r][c0 + 1] = scJ.y;
    sS[r][c0 + 2] = scJ.z; sS[r][c0 + 3] = scJ.w;

    // Pack mask bits (M is exactly 0.0/1.0).
    unsigned wI = (((mI4.x > 0.5f) ? 1u : 0u) | ((mI4.y > 0.5f) ? 2u : 0u) |
                   ((mI4.z > 0.5f) ? 4u : 0u) | ((mI4.w > 0.5f) ? 8u : 0u)) << c0;
    wI |= __shfl_xor_sync(0xffffffffu, wI, 1, 8);
    wI |= __shfl_xor_sync(0xffffffffu, wI, 2, 8);
    wI |= __shfl_xor_sync(0xffffffffu, wI, 4, 8);
    if (g == 0) g_Mbits[rowI * NT + tj] = wI;
    if (!diag) {
        const float4 mJ4 = *(const float4*)(M + baseJ);
        unsigned wJ = (((mJ4.x > 0.5f) ? 1u : 0u) | ((mJ4.y > 0.5f) ? 2u : 0u) |
                       ((mJ4.z > 0.5f) ? 4u : 0u) | ((mJ4.w > 0.5f) ? 8u : 0u)) << c0;
        wJ |= __shfl_xor_sync(0xffffffffu, wJ, 1, 8);
        wJ |= __shfl_xor_sync(0xffffffffu, wJ, 2, 8);
        wJ |= __shfl_xor_sync(0xffffffffu, wJ, 4, 8);
        if (g == 0) g_Mbits[rowJ * NT + ti] = wJ;
    }

    const float sv = *s_p;
    __syncthreads();

    const float scIv[4] = {scI.x, scI.y, scI.z, scI.w};
    const float mIv[4]  = {mI4.x, mI4.y, mI4.z, mI4.w};
    float a2v[4], uu[4];
#pragma unroll
    for (int k = 0; k < 4; k++) {
        const float avg = 0.5f * (scIv[k] + sS[c0 + k][r]);
        uu[k]  = avg - sv;
        a2v[k] = avg * mIv[k];           // exact fp32 A0 values
    }
    // Store Usym as fp16 (uint2 = 4 halves)
    {
        __half2 h01 = __floats2half2_rn(uu[0], uu[1]);
        __half2 h23 = __floats2half2_rn(uu[2], uu[3]);
        uint2 p; p.x = *(unsigned*)&h01; p.y = *(unsigned*)&h23;
        *(uint2*)(g_Uh + baseI) = p;
    }

    // Row partials of A0 (buffer 1: step 0 reads (0+1)&1 = 1).
    {
        float v = (a2v[0] + a2v[1]) + (a2v[2] + a2v[3]);
        v += __shfl_down_sync(0xffffffffu, v, 4, 8);
        v += __shfl_down_sync(0xffffffffu, v, 2, 8);
        v += __shfl_down_sync(0xffffffffu, v, 1, 8);
        if (g == 0) g_rp[1][rowI * NT + tj] = v;
    }
    if (!diag) {
#pragma unroll
        for (int k = 0; k < 4; k++) {
            float v = a2v[k];
            v += __shfl_xor_sync(0xffffffffu, v, 16);
            v += __shfl_xor_sync(0xffffffffu, v, 8);
            if (lane < 8) sRed[warp][c0 + k] = v;
        }
        __syncthreads();
        if (tid < 32) {
            float s2 = 0.f;
#pragma unroll
            for (int w = 0; w < 8; w++) s2 += sRed[w][tid];
            g_rp[1][((size_t)(b * LL) + tj * 32 + tid) * NT + ti] = s2;
        }
    }
}

// ---------------------------------------------------------------------------
// One proximal step. FIRST reads scores (A_hat0 == scores) and computes Lm0
// from the init row-partials. LAST writes A2 to out and skips state updates.
// Each block recomputes c (and Lm_t) for its 64 rows from the row-partials:
// identical FP ops on identical data in every block -> bit-identical values.
template <bool FIRST, bool LAST>
__global__ __launch_bounds__(256, 7) void step_k(const float* __restrict__ scores,
                                                 const float* __restrict__ w_p,
                                                 int t,
                                                 float* __restrict__ out) {
    const uchar2 pr = g_pairs[blockIdx.x];
    const int ti = pr.x, tj = pr.y;
    const int  b    = blockIdx.y;
    const bool diag = (ti == tj);
    const int  tid  = threadIdx.x;
    const int  r    = tid >> 3, g = tid & 7, c0 = g * 4;
    const int  warp = tid >> 5, lane = tid & 31;

    __shared__ float sAt[32][33];     // A_hat J-side, read transposed
    __shared__ float sStage[32][33];  // J-side output staging
    __shared__ float sRed[8][32];
    __shared__ float sC[64];          // c for ti rows [0..31], tj rows [32..63]

    const size_t rowI  = (size_t)(b * LL) + ti * 32 + r;
    const size_t rowJ  = (size_t)(b * LL) + tj * 32 + r;
    const size_t baseI = rowI * LL + tj * 32 + c0;
    const size_t baseJ = rowJ * LL + ti * 32 + c0;

    const unsigned long long pol = mk_pol();

    float4 ahp4, aJ4;
    if (FIRST) {
        ahp4 = *(const float4*)(scores + baseI);
        aJ4  = diag ? ahp4 : *(const float4*)(scores + baseJ);
    } else {
        ahp4 = ld_f4_el(g_Ahat + baseI, pol);
        aJ4  = diag ? ahp4 : ld_f4_el(g_Ahat + baseJ, pol);
    }
    sAt[r][c0 + 0] = aJ4.x; sAt[r][c0 + 1] = aJ4.y;
    sAt[r][c0 + 2] = aJ4.z; sAt[r][c0 + 3] = aJ4.w;

    const uint2 up = ld_u2_el(g_Uh + baseI, pol);
    const uint4 rp4 = *(const uint4*)(g_RhoP + (ti * 32 + r) * LL + tj * 32 + c0);
    const unsigned mw = g_Mbits[rowI * NT + tj];

    const float at = g_at[t];

    // --- per-row c (and Lm_t) from row-partials, deterministic ---
    {
        const int rl2 = tid >> 2, q = tid & 3;
        const int rowl = (rl2 < 32) ? (ti * 32 + rl2) : (tj * 32 + (rl2 - 32));
        const float* rpr = g_rp[(t + 1) & 1] + ((size_t)(b * LL) + rowl) * NT;
        const float4 p4 = *(const float4*)(rpr + q * 4);
        float v = (p4.x + p4.y) + (p4.z + p4.w);
        v += __shfl_xor_sync(0xffffffffu, v, 1);
        v += __shfl_xor_sync(0xffffffffu, v, 2);
        const float rd   = v - 1.0f;
        const float rpos = fmaxf(rd, 0.f);
        float lm;
        if (FIRST) lm = (*w_p) * rpos;
        else       lm = g_Lm[(t + 1) & 1][b * LL + rowl] + g_bt[t - 1] * rpos;
        if (q == 0) {
            const float sg = (rd > 0.f) ? 1.f : ((rd < 0.f) ? -1.f : 0.f);
            sC[rl2] = lm * sg;
            if (!LAST && diag && rl2 < 32) g_Lm[t & 1][b * LL + rowl] = lm;
        }
    }
    __syncthreads();

    const float ci = sC[r];
    const float ahpv[4] = {ahp4.x, ahp4.y, ahp4.z, ahp4.w};
    const __half2* rh = (const __half2*)&rp4;
    const float2 u01 = __half22float2(*(const __half2*)&up.x);
    const float2 u23 = __half22float2(*(const __half2*)&up.y);
    const float uv[4] = {u01.x, u01.y, u23.x, u23.y};

    float res[4], a2v[4];
#pragma unroll
    for (int k = 0; k < 4; k++) {
        const float m    = (float)((mw >> (c0 + k)) & 1u);
        const float cj   = sC[32 + c0 + k];
        const float2 rk  = __half22float2(rh[k]);   // (rho[i,j], rho[j,i])
        const float mult = fmaf(at * m, uv[k] - ci - cj, 1.f);
        const float pv   = fminf(fmaxf(fabsf(ahpv[k] * mult) - rk.x * at, 0.f), 1.f);
        const float aht  = sAt[c0 + k][r];
        const float tv   = fminf(fmaxf(fabsf(aht * mult) - rk.y * at, 0.f), 1.f);
        const float a2   = (pv + tv) * 0.5f * m;
        a2v[k] = a2;
        res[k] = LAST ? a2 : pv;
        sStage[c0 + k][r] = LAST ? a2 : tv;
    }

    // I-side store (coalesced float4)
    {
        float4 o = make_float4(res[0], res[1], res[2], res[3]);
        if (LAST) *(float4*)(out + baseI) = o;
        else      st_f4_el(g_Ahat + baseI, o, pol);
    }

    if (!LAST) {
        // Row partials of A2, ti rows
        float v = (a2v[0] + a2v[1]) + (a2v[2] + a2v[3]);
        v += __shfl_down_sync(0xffffffffu, v, 4, 8);
        v += __shfl_down_sync(0xffffffffu, v, 2, 8);
        v += __shfl_down_sync(0xffffffffu, v, 1, 8);
        if (g == 0) g_rp[t & 1][rowI * NT + tj] = v;
        // tj rows (off-diag only)
        if (!diag) {
#pragma unroll
            for (int k = 0; k < 4; k++) {
                float w2 = a2v[k];
                w2 += __shfl_xor_sync(0xffffffffu, w2, 16);
                w2 += __shfl_xor_sync(0xffffffffu, w2, 8);
                if (lane < 8) sRed[warp][c0 + k] = w2;
            }
        }
    }
    __syncthreads();

    // J-side store from staging (coalesced)
    if (!diag) {
        float4 o = make_float4(sStage[r][c0 + 0], sStage[r][c0 + 1],
                               sStage[r][c0 + 2], sStage[r][c0 + 3]);
        if (LAST) *(float4*)(out + baseJ) = o;
        else      st_f4_el(g_Ahat + baseJ, o, pol);
    }
    if (!LAST && !diag && tid < 32) {
        float s2 = 0.f;
#pragma unroll
        for (int w = 0; w < 8; w++) s2 += sRed[w][tid];
        g_rp[t & 1][((size_t)(b * LL) + tj * 32 + tid) * NT + ti] = s2;
    }
}

// ---------------------------------------------------------------------------
extern "C" void kernel_launch(void* const* d_in, const int* in_sizes, int n_in,
                              void* d_out, int out_size) {
    const float* scores  = (const float*)d_in[0];
    const float* M       = (const float*)d_in[1];
    const float* s_p     = (const float*)d_in[2];
    const float* w_p     = (const float*)d_in[3];
    const float* rho     = (const float*)d_in[4];
    const float* alpha_p = (const float*)d_in[5];
    const float* belt_p  = (const float*)d_in[6];
    const float* lra_p   = (const float*)d_in[7];
    const float* lrb_p   = (const float*)d_in[8];
    float* out = (float*)d_out;
    (void)in_sizes; (void)n_in; (void)out_size;

    coef_k<<<1, 256>>>(alpha_p, belt_p, lra_p, lrb_p);
    rhop_k<<<dim3(16, 16), 256>>>(rho);

    dim3 grid(NPAIRS, BB);
    init_k<<<grid, 256>>>(scores, M, s_p);

    step_k<true, false><<<grid, 256>>>(scores, w_p, 0, nullptr);
    for (int t = 1; t < NSTEPS - 1; t++)
        step_k<false, false><<<grid, 256>>>(scores, w_p, t, nullptr);
    step_k<false, true><<<grid, 256>>>(scores, w_p, NSTEPS - 1, out);
}

// round 7
// speedup vs baseline: 1.7912x; 1.0367x over previous
#include <cuda_runtime.h>
#include <cuda_fp16.h>
#include <math.h>

#define BB 64
#define LL 512
#define NSTEPS 20
#define NT 16
#define NPAIRS 136

// Persistent device scratch (allocations are forbidden in kernel_launch).
// Pair-packed state: for upper tile-pair p=(ti,tj), element (r,c) stores
// (A_hat[i,j], A_hat[j,i]) with i=ti*32+r, j=tj*32+c. One float4 = 2 elements.
__device__ float4   g_S[(size_t)BB * NPAIRS * 512];     // 71.3 MB pair state
__device__ __half   g_Uh[(size_t)BB * NPAIRS * 1024];   // 17.8 MB fp16 Usym (pair layout)
__device__ __half2  g_RhoPp[NPAIRS * 1024];             // (rho[i,j], rho[j,i]) pair layout
__device__ unsigned g_Mbits[(size_t)BB * LL * NT];      // 2 MB mask bitmap
__device__ float    g_rp[2][(size_t)BB * LL * NT];      // double-buffered row partials
__device__ float    g_Lm[2][BB * LL];                   // double-buffered multipliers
__device__ float    g_at[NSTEPS];                       // alpha * lr_alpha^t
__device__ float    g_bt[NSTEPS];                       // belt  * lr_belt^t
__device__ uchar2   g_pairs[NPAIRS];                    // (ti, tj) per linear pair id

// ---------------------------------------------------------------------------
// L2 evict_last cache-policy helpers (pin reused state in L2).
__device__ __forceinline__ unsigned long long mk_pol() {
    unsigned long long p;
    asm("createpolicy.fractional.L2::evict_last.b64 %0, 1.0;" : "=l"(p));
    return p;
}
__device__ __forceinline__ float4 ld_f4_el(const float4* a, unsigned long long pol) {
    float4 v;
    asm("ld.global.L2::cache_hint.v4.f32 {%0,%1,%2,%3}, [%4], %5;"
        : "=f"(v.x), "=f"(v.y), "=f"(v.z), "=f"(v.w)
        : "l"(a), "l"(pol));
    return v;
}
__device__ __forceinline__ void st_f4_el(float4* a, float4 v, unsigned long long pol) {
    asm volatile("st.global.L2::cache_hint.v4.f32 [%0], {%1,%2,%3,%4}, %5;"
                 :: "l"(a), "f"(v.x), "f"(v.y), "f"(v.z), "f"(v.w), "l"(pol)
                 : "memory");
}
__device__ __forceinline__ uint2 ld_u2_el(const __half* a, unsigned long long pol) {
    uint2 v;
    asm("ld.global.L2::cache_hint.v2.u32 {%0,%1}, [%2], %3;"
        : "=r"(v.x), "=r"(v.y) : "l"(a), "l"(pol));
    return v;
}

// ---------------------------------------------------------------------------
// One-time: step coefficients + pair table.
__global__ void coef_k(const float* __restrict__ alpha_p,
                       const float* __restrict__ belt_p,
                       const float* __restrict__ lra_p,
                       const float* __restrict__ lrb_p) {
    const int t = threadIdx.x;
    if (t < NSTEPS) {
        g_at[t] = (*alpha_p) * powf(*lra_p, (float)t);
        g_bt[t] = (*belt_p)  * powf(*lrb_p, (float)t);
    }
    if (t < NPAIRS) {
        int p = t, a = 0;
        while (p >= NT - a) { p -= NT - a; a++; }
        g_pairs[t] = make_uchar2((unsigned char)a, (unsigned char)(a + p));
    }
}

// ---------------------------------------------------------------------------
// Packed rho in pair layout (static, once). One block per pair.
__global__ __launch_bounds__(256) void rhop_k(const float* __restrict__ rho) {
    const uchar2 pr = g_pairs[blockIdx.x];
    const int ti = pr.x, tj = pr.y;
    const int tid = threadIdx.x;
    const int r = tid >> 3, c0 = (tid & 7) * 4;
    const float4 nat = *(const float4*)(rho + (ti * 32 + r) * LL + tj * 32 + c0);
    const float natv[4] = {nat.x, nat.y, nat.z, nat.w};
#pragma unroll
    for (int k = 0; k < 4; k++) {
        const float tr = rho[(tj * 32 + c0 + k) * LL + ti * 32 + r];
        g_RhoPp[blockIdx.x * 1024 + r * 32 + c0 + k] = __floats2half2_rn(natv[k], tr);
    }
}

// ---------------------------------------------------------------------------
// Init: pair-packed state S0 = (scores[i,j], scores[j,i]), Usym (fp16, pair
// layout), mask bitmap, and row-partials of A0 = sym(scores)*M.
__global__ __launch_bounds__(256) void init_k(const float* __restrict__ scores,
                                              const float* __restrict__ M,
                                              const float* __restrict__ s_p) {
    const int  p  = blockIdx.x;
    const uchar2 pr = g_pairs[p];
    const int ti = pr.x, tj = pr.y;
    const int  b    = blockIdx.y;
    const bool diag = (ti == tj);
    const int  tid  = threadIdx.x;
    const int  r    = tid >> 3, g = tid & 7, c0 = g * 4;
    const int  warp = tid >> 5, lane = tid & 31;

    __shared__ float sS[32][33];
    __shared__ float sRed[8][32];

    const size_t rowI  = (size_t)(b * LL) + ti * 32 + r;
    const size_t rowJ  = (size_t)(b * LL) + tj * 32 + r;
    const size_t baseI = rowI * LL + tj * 32 + c0;
    const size_t baseJ = rowJ * LL + ti * 32 + c0;

    const float4 scI = *(const float4*)(scores + baseI);
    const float4 scJ = diag ? scI : *(const float4*)(scores + baseJ);
    const float4 mI4 = *(const float4*)(M + baseI);

    sS[r][c0 + 0] = scJ.x; sS[r][c0 + 1] = scJ.y;
    sS[r][c0 + 2] = scJ.z; sS[r][c0 + 3] = scJ.w;

    // Pack mask bits (M is exactly 0.0/1.0).
    unsigned wI = (((mI4.x > 0.5f) ? 1u : 0u) | ((mI4.y > 0.5f) ? 2u : 0u) |
                   ((mI4.z > 0.5f) ? 4u : 0u) | ((mI4.w > 0.5f) ? 8u : 0u)) << c0;
    wI |= __shfl_xor_sync(0xffffffffu, wI, 1, 8);
    wI |= __shfl_xor_sync(0xffffffffu, wI, 2, 8);
    wI |= __shfl_xor_sync(0xffffffffu, wI, 4, 8);
    if (g == 0) g_Mbits[rowI * NT + tj] = wI;
    if (!diag) {
        const float4 mJ4 = *(const float4*)(M + baseJ);
        unsigned wJ = (((mJ4.x > 0.5f) ? 1u : 0u) | ((mJ4.y > 0.5f) ? 2u : 0u) |
                       ((mJ4.z > 0.5f) ? 4u : 0u) | ((mJ4.w > 0.5f) ? 8u : 0u)) << c0;
        wJ |= __shfl_xor_sync(0xffffffffu, wJ, 1, 8);
        wJ |= __shfl_xor_sync(0xffffffffu, wJ, 2, 8);
        wJ |= __shfl_xor_sync(0xffffffffu, wJ, 4, 8);
        if (g == 0) g_Mbits[rowJ * NT + ti] = wJ;
    }

    const float sv = *s_p;
    __syncthreads();

    const float scIv[4] = {scI.x, scI.y, scI.z, scI.w};
    const float mIv[4]  = {mI4.x, mI4.y, mI4.z, mI4.w};
    float a2v[4], uu[4], trv[4];
#pragma unroll
    for (int k = 0; k < 4; k++) {
        trv[k] = sS[c0 + k][r];                 // scores[j, i]
        const float avg = 0.5f * (scIv[k] + trv[k]);
        uu[k]  = avg - sv;
        a2v[k] = avg * mIv[k];                  // exact fp32 A0 values
    }
    const size_t pbase = (size_t)(b * NPAIRS + p);
    // Pair-packed S0
    {
        const size_t sidx = pbase * 512 + r * 16 + (c0 >> 1);
        g_S[sidx + 0] = make_float4(scIv[0], trv[0], scIv[1], trv[1]);
        g_S[sidx + 1] = make_float4(scIv[2], trv[2], scIv[3], trv[3]);
    }
    // Usym fp16, pair layout
    {
        __half2 h01 = __floats2half2_rn(uu[0], uu[1]);
        __half2 h23 = __floats2half2_rn(uu[2], uu[3]);
        uint2 pk; pk.x = *(unsigned*)&h01; pk.y = *(unsigned*)&h23;
        *(uint2*)(g_Uh + pbase * 1024 + r * 32 + c0) = pk;
    }

    // Row partials of A0 (buffer 1: step 0 reads (0+1)&1 = 1).
    {
        float v = (a2v[0] + a2v[1]) + (a2v[2] + a2v[3]);
        v += __shfl_down_sync(0xffffffffu, v, 4, 8);
        v += __shfl_down_sync(0xffffffffu, v, 2, 8);
        v += __shfl_down_sync(0xffffffffu, v, 1, 8);
        if (g == 0) g_rp[1][rowI * NT + tj] = v;
    }
    if (!diag) {
#pragma unroll
        for (int k = 0; k < 4; k++) {
            float v = a2v[k];
            v += __shfl_xor_sync(0xffffffffu, v, 16);
            v += __shfl_xor_sync(0xffffffffu, v, 8);
            if (lane < 8) sRed[warp][c0 + k] = v;
        }
        __syncthreads();
        if (tid < 32) {
            float s2 = 0.f;
#pragma unroll
            for (int w = 0; w < 8; w++) s2 += sRed[w][tid];
            g_rp[1][((size_t)(b * LL) + tj * 32 + tid) * NT + ti] = s2;
        }
    }
}

// ---------------------------------------------------------------------------
// One proximal step on pair-packed state. No transpose staging needed except
// in the LAST step (dense output). c (and Lm_t) recomputed per block from the
// row-partials: identical FP ops on identical data -> bit-identical values.
template <bool FIRST, bool LAST>
__global__ __launch_bounds__(256, 7) void step_k(const float* __restrict__ w_p,
                                                 int t,
                                                 float* __restrict__ out) {
    const int  p  = blockIdx.x;
    const uchar2 pr = g_pairs[p];
    const int ti = pr.x, tj = pr.y;
    const int  b    = blockIdx.y;
    const bool diag = (ti == tj);
    const int  tid  = threadIdx.x;
    const int  r    = tid >> 3, g = tid & 7, c0 = g * 4;
    const int  warp = tid >> 5, lane = tid & 31;

    constexpr int SROWS = LAST ? 32 : 1;
    __shared__ float sStage[SROWS][33];   // only used in LAST (dense transpose)
    __shared__ float sRed[8][32];
    __shared__ float sC[64];              // c for ti rows [0..31], tj rows [32..63]

    const size_t rowI = (size_t)(b * LL) + ti * 32 + r;

    const unsigned long long pol = mk_pol();

    const size_t pbase = (size_t)(b * NPAIRS + p);
    const size_t sidx  = pbase * 512 + r * 16 + (c0 >> 1);
    const float4 s01 = ld_f4_el(g_S + sidx + 0, pol);
    const float4 s23 = ld_f4_el(g_S + sidx + 1, pol);
    const uint2  up  = ld_u2_el(g_Uh + pbase * 1024 + r * 32 + c0, pol);
    const uint4  rp4 = *(const uint4*)(g_RhoPp + p * 1024 + r * 32 + c0);
    const unsigned mw = g_Mbits[rowI * NT + tj];

    const float at = g_at[t];

    // --- per-row c (and Lm_t) from row-partials, deterministic ---
    {
        const int rl2 = tid >> 2, q = tid & 3;
        const int rowl = (rl2 < 32) ? (ti * 32 + rl2) : (tj * 32 + (rl2 - 32));
        const float* rpr = g_rp[(t + 1) & 1] + ((size_t)(b * LL) + rowl) * NT;
        const float4 p4 = *(const float4*)(rpr + q * 4);
        float v = (p4.x + p4.y) + (p4.z + p4.w);
        v += __shfl_xor_sync(0xffffffffu, v, 1);
        v += __shfl_xor_sync(0xffffffffu, v, 2);
        const float rd   = v - 1.0f;
        const float rpos = fmaxf(rd, 0.f);
        float lm;
        if (FIRST) lm = (*w_p) * rpos;
        else       lm = g_Lm[(t + 1) & 1][b * LL + rowl] + g_bt[t - 1] * rpos;
        if (q == 0) {
            const float sg = (rd > 0.f) ? 1.f : ((rd < 0.f) ? -1.f : 0.f);
            sC[rl2] = lm * sg;
            if (!LAST && diag && rl2 < 32) g_Lm[t & 1][b * LL + rowl] = lm;
        }
    }
    __syncthreads();

    const float ci = sC[r];
    const float sp[4] = {s01.x, s01.z, s23.x, s23.z};   // A_hat[i,j]
    const float st[4] = {s01.y, s01.w, s23.y, s23.w};   // A_hat[j,i]
    const __half2* rh = (const __half2*)&rp4;
    const float2 u01 = __half22float2(*(const __half2*)&up.x);
    const float2 u23 = __half22float2(*(const __half2*)&up.y);
    const float uv[4] = {u01.x, u01.y, u23.x, u23.y};

    float pvv[4], tvv[4], a2v[4];
#pragma unroll
    for (int k = 0; k < 4; k++) {
        const float m    = (float)((mw >> (c0 + k)) & 1u);
        const float cj   = sC[32 + c0 + k];
        const float2 rk  = __half22float2(rh[k]);   // (rho[i,j], rho[j,i])
        const float mult = fmaf(at * m, uv[k] - ci - cj, 1.f);
        const float pv   = fminf(fmaxf(fabsf(sp[k] * mult) - rk.x * at, 0.f), 1.f);
        const float tv   = fminf(fmaxf(fabsf(st[k] * mult) - rk.y * at, 0.f), 1.f);
        const float a2   = (pv + tv) * 0.5f * m;
        pvv[k] = pv; tvv[k] = tv; a2v[k] = a2;
        if (LAST) sStage[c0 + k][r] = a2;
    }

    if (!LAST) {
        // Store updated pair state (coalesced float4 x2).
        st_f4_el(g_S + sidx + 0, make_float4(pvv[0], tvv[0], pvv[1], tvv[1]), pol);
        st_f4_el(g_S + sidx + 1, make_float4(pvv[2], tvv[2], pvv[3], tvv[3]), pol);
        // Row partials of A2, ti rows
        float v = (a2v[0] + a2v[1]) + (a2v[2] + a2v[3]);
        v += __shfl_down_sync(0xffffffffu, v, 4, 8);
        v += __shfl_down_sync(0xffffffffu, v, 2, 8);
        v += __shfl_down_sync(0xffffffffu, v, 1, 8);
        if (g == 0) g_rp[t & 1][rowI * NT + tj] = v;
        // tj rows (off-diag only; diagonal would double count)
        if (!diag) {
#pragma unroll
            for (int k = 0; k < 4; k++) {
                float w2 = a2v[k];
                w2 += __shfl_xor_sync(0xffffffffu, w2, 16);
                w2 += __shfl_xor_sync(0xffffffffu, w2, 8);
                if (lane < 8) sRed[warp][c0 + k] = w2;
            }
            __syncthreads();
            if (tid < 32) {
                float s2 = 0.f;
#pragma unroll
                for (int w = 0; w < 8; w++) s2 += sRed[w][tid];
                g_rp[t & 1][((size_t)(b * LL) + tj * 32 + tid) * NT + ti] = s2;
            }
        }
    } else {
        // Dense output: A[i,j] coalesced; A[j,i] via smem transpose.
        const size_t baseI = rowI * LL + tj * 32 + c0;
        *(float4*)(out + baseI) = make_float4(a2v[0], a2v[1], a2v[2], a2v[3]);
        __syncthreads();
        if (!diag) {
            const size_t baseJ = ((size_t)(b * LL) + tj * 32 + r) * LL + ti * 32 + c0;
            *(float4*)(out + baseJ) = make_float4(sStage[r][c0 + 0], sStage[r][c0 + 1],
                                                  sStage[r][c0 + 2], sStage[r][c0 + 3]);
        }
    }
}

// ---------------------------------------------------------------------------
extern "C" void kernel_launch(void* const* d_in, const int* in_sizes, int n_in,
                              void* d_out, int out_size) {
    const float* scores  = (const float*)d_in[0];
    const float* M       = (const float*)d_in[1];
    const float* s_p     = (const float*)d_in[2];
    const float* w_p     = (const float*)d_in[3];
    const float* rho     = (const float*)d_in[4];
    const float* alpha_p = (const float*)d_in[5];
    const float* belt_p  = (const float*)d_in[6];
    const float* lra_p   = (const float*)d_in[7];
    const float* lrb_p   = (const float*)d_in[8];
    float* out = (float*)d_out;
    (void)in_sizes; (void)n_in; (void)out_size;

    coef_k<<<1, 256>>>(alpha_p, belt_p, lra_p, lrb_p);
    rhop_k<<<NPAIRS, 256>>>(rho);

    dim3 grid(NPAIRS, BB);
    init_k<<<grid, 256>>>(scores, M, s_p);

    step_k<true, false><<<grid, 256>>>(w_p, 0, nullptr);
    for (int t = 1; t < NSTEPS - 1; t++)
        step_k<false, false><<<grid, 256>>>(w_p, t, nullptr);
    step_k<false, true><<<grid, 256>>>(w_p, NSTEPS - 1, out);
}

// round 8
// speedup vs baseline: 2.0680x; 1.1545x over previous
#include <cuda_runtime.h>
#include <cuda_fp16.h>
#include <math.h>

#define BB 64
#define LL 512
#define NSTEPS 20
#define NT 16
#define NPAIRS 136

#define QSCALE 65535.0f
#define QINV   (1.0f / 65535.0f)

// Persistent device scratch (allocations are forbidden in kernel_launch).
// Pair-packed u16 state: for upper tile-pair p=(ti,tj), element (r,c) stores
// (A_hat[i,j], A_hat[j,i]) quantized to u16 in [0,1]. One uint4 = 4 elements.
__device__ uint4    g_S[(size_t)BB * NPAIRS * 256];     // 35.7 MB pair state (u16 pairs)
__device__ __half   g_Uh[(size_t)BB * NPAIRS * 1024];   // 17.8 MB fp16 Usym (pair layout)
__device__ __half2  g_RhoPp[NPAIRS * 1024];             // (rho[i,j], rho[j,i]) pair layout
__device__ unsigned g_Mbits[(size_t)BB * LL * NT];      // 2 MB mask bitmap
__device__ float    g_rp[2][(size_t)BB * LL * NT];      // double-buffered row partials
__device__ float    g_Lm[2][BB * LL];                   // double-buffered multipliers
__device__ float    g_at[NSTEPS];                       // alpha * lr_alpha^t
__device__ float    g_bt[NSTEPS];                       // belt  * lr_belt^t
__device__ uchar2   g_pairs[NPAIRS];                    // (ti, tj) per linear pair id

// ---------------------------------------------------------------------------
// L2 evict_last cache-policy helpers (pin reused state in L2).
__device__ __forceinline__ unsigned long long mk_pol() {
    unsigned long long p;
    asm("createpolicy.fractional.L2::evict_last.b64 %0, 1.0;" : "=l"(p));
    return p;
}
__device__ __forceinline__ uint4 ld_u4_el(const uint4* a, unsigned long long pol) {
    uint4 v;
    asm("ld.global.L2::cache_hint.v4.u32 {%0,%1,%2,%3}, [%4], %5;"
        : "=r"(v.x), "=r"(v.y), "=r"(v.z), "=r"(v.w)
        : "l"(a), "l"(pol));
    return v;
}
__device__ __forceinline__ void st_u4_el(uint4* a, uint4 v, unsigned long long pol) {
    asm volatile("st.global.L2::cache_hint.v4.u32 [%0], {%1,%2,%3,%4}, %5;"
                 :: "l"(a), "r"(v.x), "r"(v.y), "r"(v.z), "r"(v.w), "l"(pol)
                 : "memory");
}
__device__ __forceinline__ uint2 ld_u2_el(const __half* a, unsigned long long pol) {
    uint2 v;
    asm("ld.global.L2::cache_hint.v2.u32 {%0,%1}, [%2], %3;"
        : "=r"(v.x), "=r"(v.y) : "l"(a), "l"(pol));
    return v;
}

__device__ __forceinline__ unsigned qpack(float a, float b) {
    return __float2uint_rn(a * QSCALE) | (__float2uint_rn(b * QSCALE) << 16);
}

// ---------------------------------------------------------------------------
// One-time: step coefficients + pair table.
__global__ void coef_k(const float* __restrict__ alpha_p,
                       const float* __restrict__ belt_p,
                       const float* __restrict__ lra_p,
                       const float* __restrict__ lrb_p) {
    const int t = threadIdx.x;
    if (t < NSTEPS) {
        g_at[t] = (*alpha_p) * powf(*lra_p, (float)t);
        g_bt[t] = (*belt_p)  * powf(*lrb_p, (float)t);
    }
    if (t < NPAIRS) {
        int p = t, a = 0;
        while (p >= NT - a) { p -= NT - a; a++; }
        g_pairs[t] = make_uchar2((unsigned char)a, (unsigned char)(a + p));
    }
}

// ---------------------------------------------------------------------------
// Packed rho in pair layout (static, once). One block per pair.
__global__ __launch_bounds__(256) void rhop_k(const float* __restrict__ rho) {
    const uchar2 pr = g_pairs[blockIdx.x];
    const int ti = pr.x, tj = pr.y;
    const int tid = threadIdx.x;
    const int r = tid >> 3, c0 = (tid & 7) * 4;
    const float4 nat = *(const float4*)(rho + (ti * 32 + r) * LL + tj * 32 + c0);
    const float natv[4] = {nat.x, nat.y, nat.z, nat.w};
#pragma unroll
    for (int k = 0; k < 4; k++) {
        const float tr = rho[(tj * 32 + c0 + k) * LL + ti * 32 + r];
        g_RhoPp[blockIdx.x * 1024 + r * 32 + c0 + k] = __floats2half2_rn(natv[k], tr);
    }
}

// ---------------------------------------------------------------------------
// Init: pair-packed u16 state S0 = (scores[i,j], scores[j,i]), Usym (fp16,
// pair layout), mask bitmap, and row-partials of A0 = sym(scores)*M.
__global__ __launch_bounds__(256) void init_k(const float* __restrict__ scores,
                                              const float* __restrict__ M,
                                              const float* __restrict__ s_p) {
    const int  p  = blockIdx.x;
    const uchar2 pr = g_pairs[p];
    const int ti = pr.x, tj = pr.y;
    const int  b    = blockIdx.y;
    const bool diag = (ti == tj);
    const int  tid  = threadIdx.x;
    const int  r    = tid >> 3, g = tid & 7, c0 = g * 4;
    const int  warp = tid >> 5, lane = tid & 31;

    __shared__ float sS[32][33];
    __shared__ float sRed[8][32];

    const size_t rowI  = (size_t)(b * LL) + ti * 32 + r;
    const size_t rowJ  = (size_t)(b * LL) + tj * 32 + r;
    const size_t baseI = rowI * LL + tj * 32 + c0;
    const size_t baseJ = rowJ * LL + ti * 32 + c0;

    const float4 scI = *(const float4*)(scores + baseI);
    const float4 scJ = diag ? scI : *(const float4*)(scores + baseJ);
    const float4 mI4 = *(const float4*)(M + baseI);

    sS[r][c0 + 0] = scJ.x; sS[r][c0 + 1] = scJ.y;
    sS[r][c0 + 2] = scJ.z; sS[r][c0 + 3] = scJ.w;

    // Pack mask bits (M is exactly 0.0/1.0).
    unsigned wI = (((mI4.x > 0.5f) ? 1u : 0u) | ((mI4.y > 0.5f) ? 2u : 0u) |
                   ((mI4.z > 0.5f) ? 4u : 0u) | ((mI4.w > 0.5f) ? 8u : 0u)) << c0;
    wI |= __shfl_xor_sync(0xffffffffu, wI, 1, 8);
    wI |= __shfl_xor_sync(0xffffffffu, wI, 2, 8);
    wI |= __shfl_xor_sync(0xffffffffu, wI, 4, 8);
    if (g == 0) g_Mbits[rowI * NT + tj] = wI;
    if (!diag) {
        const float4 mJ4 = *(const float4*)(M + baseJ);
        unsigned wJ = (((mJ4.x > 0.5f) ? 1u : 0u) | ((mJ4.y > 0.5f) ? 2u : 0u) |
                       ((mJ4.z > 0.5f) ? 4u : 0u) | ((mJ4.w > 0.5f) ? 8u : 0u)) << c0;
        wJ |= __shfl_xor_sync(0xffffffffu, wJ, 1, 8);
        wJ |= __shfl_xor_sync(0xffffffffu, wJ, 2, 8);
        wJ |= __shfl_xor_sync(0xffffffffu, wJ, 4, 8);
        if (g == 0) g_Mbits[rowJ * NT + ti] = wJ;
    }

    const float sv = *s_p;
    __syncthreads();

    const float scIv[4] = {scI.x, scI.y, scI.z, scI.w};
    const float mIv[4]  = {mI4.x, mI4.y, mI4.z, mI4.w};
    float a2v[4], uu[4], trv[4];
#pragma unroll
    for (int k = 0; k < 4; k++) {
        trv[k] = sS[c0 + k][r];                 // scores[j, i]
        const float avg = 0.5f * (scIv[k] + trv[k]);
        uu[k]  = avg - sv;
        a2v[k] = avg * mIv[k];                  // exact fp32 A0 values
    }
    const size_t pbase = (size_t)(b * NPAIRS + p);
    // Pair-packed quantized S0
    g_S[pbase * 256 + r * 8 + g] =
        make_uint4(qpack(scIv[0], trv[0]), qpack(scIv[1], trv[1]),
                   qpack(scIv[2], trv[2]), qpack(scIv[3], trv[3]));
    // Usym fp16, pair layout
    {
        __half2 h01 = __floats2half2_rn(uu[0], uu[1]);
        __half2 h23 = __floats2half2_rn(uu[2], uu[3]);
        uint2 pk; pk.x = *(unsigned*)&h01; pk.y = *(unsigned*)&h23;
        *(uint2*)(g_Uh + pbase * 1024 + r * 32 + c0) = pk;
    }

    // Row partials of A0 (buffer 1: step 0 reads (0+1)&1 = 1).
    {
        float v = (a2v[0] + a2v[1]) + (a2v[2] + a2v[3]);
        v += __shfl_down_sync(0xffffffffu, v, 4, 8);
        v += __shfl_down_sync(0xffffffffu, v, 2, 8);
        v += __shfl_down_sync(0xffffffffu, v, 1, 8);
        if (g == 0) g_rp[1][rowI * NT + tj] = v;
    }
    if (!diag) {
#pragma unroll
        for (int k = 0; k < 4; k++) {
            float v = a2v[k];
            v += __shfl_xor_sync(0xffffffffu, v, 16);
            v += __shfl_xor_sync(0xffffffffu, v, 8);
            if (lane < 8) sRed[warp][c0 + k] = v;
        }
        __syncthreads();
        if (tid < 32) {
            float s2 = 0.f;
#pragma unroll
            for (int w = 0; w < 8; w++) s2 += sRed[w][tid];
            g_rp[1][((size_t)(b * LL) + tj * 32 + tid) * NT + ti] = s2;
        }
    }
}

// ---------------------------------------------------------------------------
// One proximal step on pair-packed u16 state. c (and Lm_t) recomputed per
// block from the row-partials: identical FP ops on identical data in every
// block -> bit-identical values.
template <bool FIRST, bool LAST>
__global__ __launch_bounds__(256, 7) void step_k(const float* __restrict__ w_p,
                                                 int t,
                                                 float* __restrict__ out) {
    const int  p  = blockIdx.x;
    const uchar2 pr = g_pairs[p];
    const int ti = pr.x, tj = pr.y;
    const int  b    = blockIdx.y;
    const bool diag = (ti == tj);
    const int  tid  = threadIdx.x;
    const int  r    = tid >> 3, g = tid & 7, c0 = g * 4;
    const int  warp = tid >> 5, lane = tid & 31;

    constexpr int SROWS = LAST ? 32 : 1;
    __shared__ float sStage[SROWS][33];   // only used in LAST (dense transpose)
    __shared__ float sRed[8][32];
    __shared__ float sC[64];              // c for ti rows [0..31], tj rows [32..63]

    const size_t rowI = (size_t)(b * LL) + ti * 32 + r;

    const unsigned long long pol = mk_pol();

    const size_t pbase = (size_t)(b * NPAIRS + p);
    const size_t sidx  = pbase * 256 + r * 8 + g;
    const uint4  sq  = ld_u4_el(g_S + sidx, pol);
    const uint2  up  = ld_u2_el(g_Uh + pbase * 1024 + r * 32 + c0, pol);
    const uint4  rp4 = *(const uint4*)(g_RhoPp + p * 1024 + r * 32 + c0);
    const unsigned mw = g_Mbits[rowI * NT + tj];

    const float at = g_at[t];

    // --- per-row c (and Lm_t) from row-partials, deterministic ---
    {
        const int rl2 = tid >> 2, q = tid & 3;
        const int rowl = (rl2 < 32) ? (ti * 32 + rl2) : (tj * 32 + (rl2 - 32));
        const float* rpr = g_rp[(t + 1) & 1] + ((size_t)(b * LL) + rowl) * NT;
        const float4 p4 = *(const float4*)(rpr + q * 4);
        float v = (p4.x + p4.y) + (p4.z + p4.w);
        v += __shfl_xor_sync(0xffffffffu, v, 1);
        v += __shfl_xor_sync(0xffffffffu, v, 2);
        const float rd   = v - 1.0f;
        const float rpos = fmaxf(rd, 0.f);
        float lm;
        if (FIRST) lm = (*w_p) * rpos;
        else       lm = g_Lm[(t + 1) & 1][b * LL + rowl] + g_bt[t - 1] * rpos;
        if (q == 0) {
            const float sg = (rd > 0.f) ? 1.f : ((rd < 0.f) ? -1.f : 0.f);
            sC[rl2] = lm * sg;
            if (!LAST && diag && rl2 < 32) g_Lm[t & 1][b * LL + rowl] = lm;
        }
    }
    __syncthreads();

    const float ci = sC[r];
    const unsigned sqs[4] = {sq.x, sq.y, sq.z, sq.w};
    const __half2* rh = (const __half2*)&rp4;
    const float2 u01 = __half22float2(*(const __half2*)&up.x);
    const float2 u23 = __half22float2(*(const __half2*)&up.y);
    const float uv[4] = {u01.x, u01.y, u23.x, u23.y};

    float pvv[4], tvv[4], a2v[4];
#pragma unroll
    for (int k = 0; k < 4; k++) {
        const float m    = (float)((mw >> (c0 + k)) & 1u);
        const float cj   = sC[32 + c0 + k];
        const float2 rk  = __half22float2(rh[k]);   // (rho[i,j], rho[j,i])
        const float sp   = (float)(sqs[k] & 0xffffu) * QINV;   // A_hat[i,j]
        const float st   = (float)(sqs[k] >> 16)     * QINV;   // A_hat[j,i]
        const float mult = fmaf(at * m, uv[k] - ci - cj, 1.f);
        const float pv   = fminf(fmaxf(fabsf(sp * mult) - rk.x * at, 0.f), 1.f);
        const float tv   = fminf(fmaxf(fabsf(st * mult) - rk.y * at, 0.f), 1.f);
        const float a2   = (pv + tv) * 0.5f * m;
        pvv[k] = pv; tvv[k] = tv; a2v[k] = a2;
        if (LAST) sStage[c0 + k][r] = a2;
    }

    if (!LAST) {
        // Store updated quantized pair state (one coalesced uint4).
        st_u4_el(g_S + sidx,
                 make_uint4(qpack(pvv[0], tvv[0]), qpack(pvv[1], tvv[1]),
                            qpack(pvv[2], tvv[2]), qpack(pvv[3], tvv[3])), pol);
        // Row partials of A2, ti rows
        float v = (a2v[0] + a2v[1]) + (a2v[2] + a2v[3]);
        v += __shfl_down_sync(0xffffffffu, v, 4, 8);
        v += __shfl_down_sync(0xffffffffu, v, 2, 8);
        v += __shfl_down_sync(0xffffffffu, v, 1, 8);
        if (g == 0) g_rp[t & 1][rowI * NT + tj] = v;
        // tj rows (off-diag only; diagonal would double count)
        if (!diag) {
#pragma unroll
            for (int k = 0; k < 4; k++) {
                float w2 = a2v[k];
                w2 += __shfl_xor_sync(0xffffffffu, w2, 16);
                w2 += __shfl_xor_sync(0xffffffffu, w2, 8);
                if (lane < 8) sRed[warp][c0 + k] = w2;
            }
            __syncthreads();
            if (tid < 32) {
                float s2 = 0.f;
#pragma unroll
                for (int w = 0; w < 8; w++) s2 += sRed[w][tid];
                g_rp[t & 1][((size_t)(b * LL) + tj * 32 + tid) * NT + ti] = s2;
            }
        }
    } else {
        // Dense output: A[i,j] coalesced; A[j,i] via smem transpose.
        const size_t baseI = rowI * LL + tj * 32 + c0;
        *(float4*)(out + baseI) = make_float4(a2v[0], a2v[1], a2v[2], a2v[3]);
        __syncthreads();
        if (!diag) {
            const size_t baseJ = ((size_t)(b * LL) + tj * 32 + r) * LL + ti * 32 + c0;
            *(float4*)(out + baseJ) = make_float4(sStage[r][c0 + 0], sStage[r][c0 + 1],
                                                  sStage[r][c0 + 2], sStage[r][c0 + 3]);
        }
    }
}

// ---------------------------------------------------------------------------
extern "C" void kernel_launch(void* const* d_in, const int* in_sizes, int n_in,
                              void* d_out, int out_size) {
    const float* scores  = (const float*)d_in[0];
    const float* M       = (const float*)d_in[1];
    const float* s_p     = (const float*)d_in[2];
    const float* w_p     = (const float*)d_in[3];
    const float* rho     = (const float*)d_in[4];
    const float* alpha_p = (const float*)d_in[5];
    const float* belt_p  = (const float*)d_in[6];
    const float* lra_p   = (const float*)d_in[7];
    const float* lrb_p   = (const float*)d_in[8];
    float* out = (float*)d_out;
    (void)in_sizes; (void)n_in; (void)out_size;

    coef_k<<<1, 256>>>(alpha_p, belt_p, lra_p, lrb_p);
    rhop_k<<<NPAIRS, 256>>>(rho);

    dim3 grid(NPAIRS, BB);
    init_k<<<grid, 256>>>(scores, M, s_p);

    step_k<true, false><<<grid, 256>>>(w_p, 0, nullptr);
    for (int t = 1; t < NSTEPS - 1; t++)
        step_k<false, false><<<grid, 256>>>(w_p, t, nullptr);
    step_k<false, true><<<grid, 256>>>(w_p, NSTEPS - 1, out);
}

// round 11
// speedup vs baseline: 2.1023x; 1.0166x over previous
#include <cuda_runtime.h>
#include <cuda_fp16.h>
#include <math.h>

#define BB 64
#define LL 512
#define NSTEPS 20
#define NT 16
#define NPAIRS 136

#define QSCALE 65535.0f
#define QINV   (1.0f / 65535.0f)

// Persistent device scratch (allocations are forbidden in kernel_launch).
// Pair-packed u16 state: for upper tile-pair p=(ti,tj), element (r,c) stores
// (A_hat[i,j], A_hat[j,i]) quantized to u16 in [0,1]. One uint4 = 4 elements.
__device__ uint4    g_S[(size_t)BB * NPAIRS * 256];     // 35.7 MB pair state (u16 pairs)
__device__ __half   g_Uh[(size_t)BB * NPAIRS * 1024];   // 17.8 MB fp16 Usym (pair layout)
__device__ __half2  g_RhoPp[NPAIRS * 1024];             // (rho[i,j], rho[j,i]) pair layout
__device__ unsigned g_Mbits[(size_t)BB * LL * NT];      // 2 MB mask bitmap
__device__ float    g_rp[2][(size_t)BB * LL * NT];      // double-buffered row partials
__device__ float    g_Lm[2][BB * LL];                   // double-buffered multipliers
__device__ float    g_at[NSTEPS];                       // alpha * lr_alpha^t
__device__ float    g_bt[NSTEPS];                       // belt  * lr_belt^t
__device__ uchar2   g_pairs[NPAIRS];                    // (ti, tj) per linear pair id

// ---------------------------------------------------------------------------
// L2 evict_last cache-policy helpers (pin reused state in L2).
__device__ __forceinline__ unsigned long long mk_pol() {
    unsigned long long p;
    asm("createpolicy.fractional.L2::evict_last.b64 %0, 1.0;" : "=l"(p));
    return p;
}
__device__ __forceinline__ uint4 ld_u4_el(const uint4* a, unsigned long long pol) {
    uint4 v;
    asm("ld.global.L2::cache_hint.v4.u32 {%0,%1,%2,%3}, [%4], %5;"
        : "=r"(v.x), "=r"(v.y), "=r"(v.z), "=r"(v.w)
        : "l"(a), "l"(pol));
    return v;
}
__device__ __forceinline__ void st_u4_el(uint4* a, uint4 v, unsigned long long pol) {
    asm volatile("st.global.L2::cache_hint.v4.u32 [%0], {%1,%2,%3,%4}, %5;"
                 :: "l"(a), "r"(v.x), "r"(v.y), "r"(v.z), "r"(v.w), "l"(pol)
                 : "memory");
}
__device__ __forceinline__ uint2 ld_u2_el(const __half* a, unsigned long long pol) {
    uint2 v;
    asm("ld.global.L2::cache_hint.v2.u32 {%0,%1}, [%2], %3;"
        : "=r"(v.x), "=r"(v.y) : "l"(a), "l"(pol));
    return v;
}

__device__ __forceinline__ unsigned qpack(float a, float b) {
    return __float2uint_rn(a * QSCALE) | (__float2uint_rn(b * QSCALE) << 16);
}
// Pack two q-domain values (already in [0,65535]).
__device__ __forceinline__ unsigned qpackq(float a, float b) {
    return __float2uint_rn(a) | (__float2uint_rn(b) << 16);
}

// ---------------------------------------------------------------------------
// One-time: step coefficients + pair table.
__global__ void coef_k(const float* __restrict__ alpha_p,
                       const float* __restrict__ belt_p,
                       const float* __restrict__ lra_p,
                       const float* __restrict__ lrb_p) {
    const int t = threadIdx.x;
    if (t < NSTEPS) {
        g_at[t] = (*alpha_p) * powf(*lra_p, (float)t);
        g_bt[t] = (*belt_p)  * powf(*lrb_p, (float)t);
    }
    if (t < NPAIRS) {
        int p = t, a = 0;
        while (p >= NT - a) { p -= NT - a; a++; }
        g_pairs[t] = make_uchar2((unsigned char)a, (unsigned char)(a + p));
    }
}

// ---------------------------------------------------------------------------
// Packed rho in pair layout (static, once). One block per pair.
__global__ __launch_bounds__(256) void rhop_k(const float* __restrict__ rho) {
    const uchar2 pr = g_pairs[blockIdx.x];
    const int ti = pr.x, tj = pr.y;
    const int tid = threadIdx.x;
    const int r = tid >> 3, c0 = (tid & 7) * 4;
    const float4 nat = *(const float4*)(rho + (ti * 32 + r) * LL + tj * 32 + c0);
    const float natv[4] = {nat.x, nat.y, nat.z, nat.w};
#pragma unroll
    for (int k = 0; k < 4; k++) {
        const float tr = rho[(tj * 32 + c0 + k) * LL + ti * 32 + r];
        g_RhoPp[blockIdx.x * 1024 + r * 32 + c0 + k] = __floats2half2_rn(natv[k], tr);
    }
}

// ---------------------------------------------------------------------------
// Init: pair-packed u16 state S0 = (scores[i,j], scores[j,i]), Usym (fp16,
// pair layout), mask bitmap, and row-partials of A0 = sym(scores)*M.
__global__ __launch_bounds__(256) void init_k(const float* __restrict__ scores,
                                              const float* __restrict__ M,
                                              const float* __restrict__ s_p) {
    const int  p  = blockIdx.x;
    const uchar2 pr = g_pairs[p];
    const int ti = pr.x, tj = pr.y;
    const int  b    = blockIdx.y;
    const bool diag = (ti == tj);
    const int  tid  = threadIdx.x;
    const int  r    = tid >> 3, g = tid & 7, c0 = g * 4;
    const int  warp = tid >> 5, lane = tid & 31;

    __shared__ float sS[32][33];
    __shared__ float sRed[8][32];

    const size_t rowI  = (size_t)(b * LL) + ti * 32 + r;
    const size_t rowJ  = (size_t)(b * LL) + tj * 32 + r;
    const size_t baseI = rowI * LL + tj * 32 + c0;
    const size_t baseJ = rowJ * LL + ti * 32 + c0;

    const float4 scI = *(const float4*)(scores + baseI);
    const float4 scJ = diag ? scI : *(const float4*)(scores + baseJ);
    const float4 mI4 = *(const float4*)(M + baseI);

    sS[r][c0 + 0] = scJ.x; sS[r][c0 + 1] = scJ.y;
    sS[r][c0 + 2] = scJ.z; sS[r][c0 + 3] = scJ.w;

    // Pack mask bits (M is exactly 0.0/1.0).
    unsigned wI = (((mI4.x > 0.5f) ? 1u : 0u) | ((mI4.y > 0.5f) ? 2u : 0u) |
                   ((mI4.z > 0.5f) ? 4u : 0u) | ((mI4.w > 0.5f) ? 8u : 0u)) << c0;
    wI |= __shfl_xor_sync(0xffffffffu, wI, 1, 8);
    wI |= __shfl_xor_sync(0xffffffffu, wI, 2, 8);
    wI |= __shfl_xor_sync(0xffffffffu, wI, 4, 8);
    if (g == 0) g_Mbits[rowI * NT + tj] = wI;
    if (!diag) {
        const float4 mJ4 = *(const float4*)(M + baseJ);
        unsigned wJ = (((mJ4.x > 0.5f) ? 1u : 0u) | ((mJ4.y > 0.5f) ? 2u : 0u) |
                       ((mJ4.z > 0.5f) ? 4u : 0u) | ((mJ4.w > 0.5f) ? 8u : 0u)) << c0;
        wJ |= __shfl_xor_sync(0xffffffffu, wJ, 1, 8);
        wJ |= __shfl_xor_sync(0xffffffffu, wJ, 2, 8);
        wJ |= __shfl_xor_sync(0xffffffffu, wJ, 4, 8);
        if (g == 0) g_Mbits[rowJ * NT + ti] = wJ;
    }

    const float sv = *s_p;
    __syncthreads();

    const float scIv[4] = {scI.x, scI.y, scI.z, scI.w};
    const float mIv[4]  = {mI4.x, mI4.y, mI4.z, mI4.w};
    float a2v[4], uu[4], trv[4];
#pragma unroll
    for (int k = 0; k < 4; k++) {
        trv[k] = sS[c0 + k][r];                 // scores[j, i]
        const float avg = 0.5f * (scIv[k] + trv[k]);
        uu[k]  = avg - sv;
        a2v[k] = avg * mIv[k];                  // exact fp32 A0 values
    }
    const size_t pbase = (size_t)(b * NPAIRS + p);
    // Pair-packed quantized S0
    g_S[pbase * 256 + r * 8 + g] =
        make_uint4(qpack(scIv[0], trv[0]), qpack(scIv[1], trv[1]),
                   qpack(scIv[2], trv[2]), qpack(scIv[3], trv[3]));
    // Usym fp16, pair layout
    {
        __half2 h01 = __floats2half2_rn(uu[0], uu[1]);
        __half2 h23 = __floats2half2_rn(uu[2], uu[3]);
        uint2 pk; pk.x = *(unsigned*)&h01; pk.y = *(unsigned*)&h23;
        *(uint2*)(g_Uh + pbase * 1024 + r * 32 + c0) = pk;
    }

    // Row partials of A0 (buffer 1: step 0 reads (0+1)&1 = 1).
    {
        float v = (a2v[0] + a2v[1]) + (a2v[2] + a2v[3]);
        v += __shfl_down_sync(0xffffffffu, v, 4, 8);
        v += __shfl_down_sync(0xffffffffu, v, 2, 8);
        v += __shfl_down_sync(0xffffffffu, v, 1, 8);
        if (g == 0) g_rp[1][rowI * NT + tj] = v;
    }
    if (!diag) {
#pragma unroll
        for (int k = 0; k < 4; k++) {
            float v = a2v[k];
            v += __shfl_xor_sync(0xffffffffu, v, 16);
            v += __shfl_xor_sync(0xffffffffu, v, 8);
            if (lane < 8) sRed[warp][c0 + k] = v;
        }
        __syncthreads();
        if (tid < 32) {
            float s2 = 0.f;
#pragma unroll
            for (int w = 0; w < 8; w++) s2 += sRed[w][tid];
            g_rp[1][((size_t)(b * LL) + tj * 32 + tid) * NT + ti] = s2;
        }
    }
}

// ---------------------------------------------------------------------------
// One proximal step on pair-packed u16 state, q-domain arithmetic.
// c (and Lm_t) recomputed per block from the row-partials by 2 warps only:
// identical FP ops on identical data in every block -> bit-identical values.
template <bool FIRST, bool LAST>
__global__ __launch_bounds__(256, 7) void step_k(const float* __restrict__ w_p,
                                                 int t,
                                                 float* __restrict__ out) {
    const int  p  = blockIdx.x;
    const uchar2 pr = g_pairs[p];
    const int ti = pr.x, tj = pr.y;
    const int  b    = blockIdx.y;
    const bool diag = (ti == tj);
    const int  tid  = threadIdx.x;
    const int  r    = tid >> 3, g = tid & 7, c0 = g * 4;
    const int  warp = tid >> 5, lane = tid & 31;

    constexpr int SROWS = LAST ? 32 : 1;
    __shared__ float sStage[SROWS][33];   // only used in LAST (dense transpose)
    __shared__ float sRed[8][32];
    __shared__ float sC[64];              // c for ti rows [0..31], tj rows [32..63]

    const size_t rowI = (size_t)(b * LL) + ti * 32 + r;

    const unsigned long long pol = mk_pol();

    const size_t pbase = (size_t)(b * NPAIRS + p);
    const size_t sidx  = pbase * 256 + r * 8 + g;
    const uint4  sq  = ld_u4_el(g_S + sidx, pol);
    const uint2  up  = ld_u2_el(g_Uh + pbase * 1024 + r * 32 + c0, pol);
    const uint4  rp4 = *(const uint4*)(g_RhoPp + p * 1024 + r * 32 + c0);
    const unsigned mw = g_Mbits[rowI * NT + tj];

    const float at  = g_at[t];
    const float atq = at * QSCALE;

    // --- per-row c (and Lm_t): 2 warps, one row per thread, deterministic ---
    if (tid < 64) {
        const int rowl = (tid < 32) ? (ti * 32 + tid) : (tj * 32 + (tid - 32));
        const float* rpr = g_rp[(t + 1) & 1] + ((size_t)(b * LL) + rowl) * NT;
        const float4 p0 = *(const float4*)(rpr + 0);
        const float4 p1 = *(const float4*)(rpr + 4);
        const float4 p2 = *(const float4*)(rpr + 8);
        const float4 p3 = *(const float4*)(rpr + 12);
        const float v = (((p0.x + p0.y) + (p0.z + p0.w)) +
                         ((p1.x + p1.y) + (p1.z + p1.w))) +
                        (((p2.x + p2.y) + (p2.z + p2.w)) +
                         ((p3.x + p3.y) + (p3.z + p3.w)));
        const float rd   = v - 1.0f;
        const float rpos = fmaxf(rd, 0.f);
        float lm;
        if (FIRST) lm = (*w_p) * rpos;
        else       lm = g_Lm[(t + 1) & 1][b * LL + rowl] + g_bt[t - 1] * rpos;
        const float sg = (rd > 0.f) ? 1.f : ((rd < 0.f) ? -1.f : 0.f);
        sC[tid] = lm * sg;
        if (!LAST && diag && tid < 32) g_Lm[t & 1][b * LL + rowl] = lm;
    }
    __syncthreads();

    const float ci = sC[r];
    const unsigned sqs[4] = {sq.x, sq.y, sq.z, sq.w};
    const __half2* rh = (const __half2*)&rp4;
    const float2 u01 = __half22float2(*(const __half2*)&up.x);
    const float2 u23 = __half22float2(*(const __half2*)&up.y);
    const float uv[4] = {u01.x, u01.y, u23.x, u23.y};

    float pvq[4], tvq[4], a2q[4];
#pragma unroll
    for (int k = 0; k < 4; k++) {
        const bool  mk   = (mw >> (c0 + k)) & 1u;
        const float du   = uv[k] - (ci + sC[32 + c0 + k]);
        const float mult = mk ? fmaf(at, du, 1.f) : 1.f;
        const float2 rk  = __half22float2(rh[k]);   // (rho[i,j], rho[j,i])
        const float spq  = (float)(sqs[k] & 0xffffu);   // q-domain A_hat[i,j]
        const float stq  = (float)(sqs[k] >> 16);       // q-domain A_hat[j,i]
        const float pv = fminf(fmaxf(fabsf(spq * mult) - rk.x * atq, 0.f), QSCALE);
        const float tv = fminf(fmaxf(fabsf(stq * mult) - rk.y * atq, 0.f), QSCALE);
        pvq[k] = pv; tvq[k] = tv;
        a2q[k] = mk ? (pv + tv) : 0.f;               // q-domain, x2 scale
        if (LAST) sStage[c0 + k][r] = a2q[k];
    }

    constexpr float HQ = 0.5f * QINV;

    if (!LAST) {
        // Store updated quantized pair state (one coalesced uint4).
        st_u4_el(g_S + sidx,
                 make_uint4(qpackq(pvq[0], tvq[0]), qpackq(pvq[1], tvq[1]),
                            qpackq(pvq[2], tvq[2]), qpackq(pvq[3], tvq[3])), pol);
        // Row partials of A2, ti rows (sum in q units, scale once).
        float v = (a2q[0] + a2q[1]) + (a2q[2] + a2q[3]);
        v += __shfl_down_sync(0xffffffffu, v, 4, 8);
        v += __shfl_down_sync(0xffffffffu, v, 2, 8);
        v += __shfl_down_sync(0xffffffffu, v, 1, 8);
        if (g == 0) g_rp[t & 1][rowI * NT + tj] = v * HQ;
        // tj rows (off-diag only; diagonal would double count)
        if (!diag) {
#pragma unroll
            for (int k = 0; k < 4; k++) {
                float w2 = a2q[k];
                w2 += __shfl_xor_sync(0xffffffffu, w2, 16);
                w2 += __shfl_xor_sync(0xffffffffu, w2, 8);
                if (lane < 8) sRed[warp][c0 + k] = w2;
            }
            __syncthreads();
            if (tid < 32) {
                float s2 = 0.f;
#pragma unroll
                for (int w = 0; w < 8; w++) s2 += sRed[w][tid];
                g_rp[t & 1][((size_t)(b * LL) + tj * 32 + tid) * NT + ti] = s2 * HQ;
            }
        }
    } else {
        // Dense output: A[i,j] coalesced; A[j,i] via smem transpose.
        const size_t baseI = rowI * LL + tj * 32 + c0;
        *(float4*)(out + baseI) = make_float4(a2q[0] * HQ, a2q[1] * HQ,
                                              a2q[2] * HQ, a2q[3] * HQ);
        __syncthreads();
        if (!diag) {
            const size_t baseJ = ((size_t)(b * LL) + tj * 32 + r) * LL + ti * 32 + c0;
            *(float4*)(out + baseJ) = make_float4(sStage[r][c0 + 0] * HQ,
                                                  sStage[r][c0 + 1] * HQ,
                                                  sStage[r][c0 + 2] * HQ,
                                                  sStage[r][c0 + 3] * HQ);
        }
    }
}

// ---------------------------------------------------------------------------
extern "C" void kernel_launch(void* const* d_in, const int* in_sizes, int n_in,
                              void* d_out, int out_size) {
    const float* scores  = (const float*)d_in[0];
    const float* M       = (const float*)d_in[1];
    const float* s_p     = (const float*)d_in[2];
    const float* w_p     = (const float*)d_in[3];
    const float* rho     = (const float*)d_in[4];
    const float* alpha_p = (const float*)d_in[5];
    const float* belt_p  = (const float*)d_in[6];
    const float* lra_p   = (const float*)d_in[7];
    const float* lrb_p   = (const float*)d_in[8];
    float* out = (float*)d_out;
    (void)in_sizes; (void)n_in; (void)out_size;

    coef_k<<<1, 256>>>(alpha_p, belt_p, lra_p, lrb_p);
    rhop_k<<<NPAIRS, 256>>>(rho);

    dim3 grid(NPAIRS, BB);
    init_k<<<grid, 256>>>(scores, M, s_p);

    step_k<true, false><<<grid, 256>>>(w_p, 0, nullptr);
    for (int t = 1; t < NSTEPS - 1; t++)
        step_k<false, false><<<grid, 256>>>(w_p, t, nullptr);
    step_k<false, true><<<grid, 256>>>(w_p, NSTEPS - 1, out);
}

// round 12
// speedup vs baseline: 2.2668x; 1.0782x over previous
#include <cuda_runtime.h>
#include <cuda_fp16.h>
#include <math.h>

#define BB 64
#define LL 512
#define NSTEPS 20
#define NT 16
#define NPAIRS 136

#define QSCALE 65535.0f
#define QINV   (1.0f / 65535.0f)

// Persistent device scratch (allocations are forbidden in kernel_launch).
// Pair-packed u16 state: for upper tile-pair p=(ti,tj), element (r,c) stores
// (A_hat[i,j], A_hat[j,i]) quantized to u16 in [0,1]. One uint4 = 4 elements.
__device__ uint4    g_S[(size_t)BB * NPAIRS * 256];     // 35.7 MB pair state (u16 pairs)
__device__ __half   g_Uh[(size_t)BB * NPAIRS * 1024];   // 17.8 MB fp16 Usym (pair layout)
__device__ __half2  g_RhoPp[NPAIRS * 1024];             // (rho[i,j], rho[j,i]) pair layout
__device__ unsigned g_Mbits[(size_t)BB * LL * NT];      // 2 MB mask bitmap
__device__ float    g_rp[2][(size_t)BB * LL * NT];      // double-buffered row partials
__device__ float    g_Lm[2][BB * LL];                   // double-buffered multipliers
__device__ float    g_at[NSTEPS];                       // alpha * lr_alpha^t
__device__ float    g_bt[NSTEPS];                       // belt  * lr_belt^t
__device__ uchar2   g_pairs[NPAIRS];                    // (ti, tj) per linear pair id

// ---------------------------------------------------------------------------
// L2 evict_last cache-policy helpers (pin reused state in L2).
__device__ __forceinline__ unsigned long long mk_pol() {
    unsigned long long p;
    asm("createpolicy.fractional.L2::evict_last.b64 %0, 1.0;" : "=l"(p));
    return p;
}
__device__ __forceinline__ uint4 ld_u4_el(const uint4* a, unsigned long long pol) {
    uint4 v;
    asm("ld.global.L2::cache_hint.v4.u32 {%0,%1,%2,%3}, [%4], %5;"
        : "=r"(v.x), "=r"(v.y), "=r"(v.z), "=r"(v.w)
        : "l"(a), "l"(pol));
    return v;
}
__device__ __forceinline__ void st_u4_el(uint4* a, uint4 v, unsigned long long pol) {
    asm volatile("st.global.L2::cache_hint.v4.u32 [%0], {%1,%2,%3,%4}, %5;"
                 :: "l"(a), "r"(v.x), "r"(v.y), "r"(v.z), "r"(v.w), "l"(pol)
                 : "memory");
}
__device__ __forceinline__ uint2 ld_u2_el(const __half* a, unsigned long long pol) {
    uint2 v;
    asm("ld.global.L2::cache_hint.v2.u32 {%0,%1}, [%2], %3;"
        : "=r"(v.x), "=r"(v.y) : "l"(a), "l"(pol));
    return v;
}

__device__ __forceinline__ unsigned qpack(float a, float b) {
    return __float2uint_rn(a * QSCALE) | (__float2uint_rn(b * QSCALE) << 16);
}
// Pack two q-domain values (already in [0,65535]).
__device__ __forceinline__ unsigned qpackq(float a, float b) {
    return __float2uint_rn(a) | (__float2uint_rn(b) << 16);
}

// ---------------------------------------------------------------------------
// One-time: step coefficients + pair table.
__global__ void coef_k(const float* __restrict__ alpha_p,
                       const float* __restrict__ belt_p,
                       const float* __restrict__ lra_p,
                       const float* __restrict__ lrb_p) {
    const int t = threadIdx.x;
    if (t < NSTEPS) {
        g_at[t] = (*alpha_p) * powf(*lra_p, (float)t);
        g_bt[t] = (*belt_p)  * powf(*lrb_p, (float)t);
    }
    if (t < NPAIRS) {
        int p = t, a = 0;
        while (p >= NT - a) { p -= NT - a; a++; }
        g_pairs[t] = make_uchar2((unsigned char)a, (unsigned char)(a + p));
    }
}

// ---------------------------------------------------------------------------
// Packed rho in pair layout (static, once). One block per pair.
__global__ __launch_bounds__(256) void rhop_k(const float* __restrict__ rho) {
    const uchar2 pr = g_pairs[blockIdx.x];
    const int ti = pr.x, tj = pr.y;
    const int tid = threadIdx.x;
    const int r = tid >> 3, c0 = (tid & 7) * 4;
    const float4 nat = *(const float4*)(rho + (ti * 32 + r) * LL + tj * 32 + c0);
    const float natv[4] = {nat.x, nat.y, nat.z, nat.w};
#pragma unroll
    for (int k = 0; k < 4; k++) {
        const float tr = rho[(tj * 32 + c0 + k) * LL + ti * 32 + r];
        g_RhoPp[blockIdx.x * 1024 + r * 32 + c0 + k] = __floats2half2_rn(natv[k], tr);
    }
}

// ---------------------------------------------------------------------------
// Init: pair-packed u16 state S0 = (scores[i,j], scores[j,i]), Usym (fp16,
// pair layout), mask bitmap, and row-partials of A0 = sym(scores)*M.
__global__ __launch_bounds__(256) void init_k(const float* __restrict__ scores,
                                              const float* __restrict__ M,
                                              const float* __restrict__ s_p) {
    const int  p  = blockIdx.x;
    const uchar2 pr = g_pairs[p];
    const int ti = pr.x, tj = pr.y;
    const int  b    = blockIdx.y;
    const bool diag = (ti == tj);
    const int  tid  = threadIdx.x;
    const int  r    = tid >> 3, g = tid & 7, c0 = g * 4;
    const int  warp = tid >> 5, lane = tid & 31;

    __shared__ float sS[32][33];
    __shared__ float sRed[8][32];

    const size_t rowI  = (size_t)(b * LL) + ti * 32 + r;
    const size_t rowJ  = (size_t)(b * LL) + tj * 32 + r;
    const size_t baseI = rowI * LL + tj * 32 + c0;
    const size_t baseJ = rowJ * LL + ti * 32 + c0;

    const float4 scI = *(const float4*)(scores + baseI);
    const float4 scJ = diag ? scI : *(const float4*)(scores + baseJ);
    const float4 mI4 = *(const float4*)(M + baseI);

    sS[r][c0 + 0] = scJ.x; sS[r][c0 + 1] = scJ.y;
    sS[r][c0 + 2] = scJ.z; sS[r][c0 + 3] = scJ.w;

    // Pack mask bits (M is exactly 0.0/1.0).
    unsigned wI = (((mI4.x > 0.5f) ? 1u : 0u) | ((mI4.y > 0.5f) ? 2u : 0u) |
                   ((mI4.z > 0.5f) ? 4u : 0u) | ((mI4.w > 0.5f) ? 8u : 0u)) << c0;
    wI |= __shfl_xor_sync(0xffffffffu, wI, 1, 8);
    wI |= __shfl_xor_sync(0xffffffffu, wI, 2, 8);
    wI |= __shfl_xor_sync(0xffffffffu, wI, 4, 8);
    if (g == 0) g_Mbits[rowI * NT + tj] = wI;
    if (!diag) {
        const float4 mJ4 = *(const float4*)(M + baseJ);
        unsigned wJ = (((mJ4.x > 0.5f) ? 1u : 0u) | ((mJ4.y > 0.5f) ? 2u : 0u) |
                       ((mJ4.z > 0.5f) ? 4u : 0u) | ((mJ4.w > 0.5f) ? 8u : 0u)) << c0;
        wJ |= __shfl_xor_sync(0xffffffffu, wJ, 1, 8);
        wJ |= __shfl_xor_sync(0xffffffffu, wJ, 2, 8);
        wJ |= __shfl_xor_sync(0xffffffffu, wJ, 4, 8);
        if (g == 0) g_Mbits[rowJ * NT + ti] = wJ;
    }

    const float sv = *s_p;
    __syncthreads();

    const float scIv[4] = {scI.x, scI.y, scI.z, scI.w};
    const float mIv[4]  = {mI4.x, mI4.y, mI4.z, mI4.w};
    float a2v[4], uu[4], trv[4];
#pragma unroll
    for (int k = 0; k < 4; k++) {
        trv[k] = sS[c0 + k][r];                 // scores[j, i]
        const float avg = 0.5f * (scIv[k] + trv[k]);
        uu[k]  = avg - sv;
        a2v[k] = avg * mIv[k];                  // exact fp32 A0 values
    }
    const size_t pbase = (size_t)(b * NPAIRS + p);
    // Pair-packed quantized S0
    g_S[pbase * 256 + r * 8 + g] =
        make_uint4(qpack(scIv[0], trv[0]), qpack(scIv[1], trv[1]),
                   qpack(scIv[2], trv[2]), qpack(scIv[3], trv[3]));
    // Usym fp16, pair layout
    {
        __half2 h01 = __floats2half2_rn(uu[0], uu[1]);
        __half2 h23 = __floats2half2_rn(uu[2], uu[3]);
        uint2 pk; pk.x = *(unsigned*)&h01; pk.y = *(unsigned*)&h23;
        *(uint2*)(g_Uh + pbase * 1024 + r * 32 + c0) = pk;
    }

    // Row partials of A0 (buffer 1: step 0 reads (0+1)&1 = 1).
    {
        float v = (a2v[0] + a2v[1]) + (a2v[2] + a2v[3]);
        v += __shfl_down_sync(0xffffffffu, v, 4, 8);
        v += __shfl_down_sync(0xffffffffu, v, 2, 8);
        v += __shfl_down_sync(0xffffffffu, v, 1, 8);
        if (g == 0) g_rp[1][rowI * NT + tj] = v;
    }
    if (!diag) {
#pragma unroll
        for (int k = 0; k < 4; k++) {
            float v = a2v[k];
            v += __shfl_xor_sync(0xffffffffu, v, 16);
            v += __shfl_xor_sync(0xffffffffu, v, 8);
            if (lane < 8) sRed[warp][c0 + k] = v;
        }
        __syncthreads();
        if (tid < 32) {
            float s2 = 0.f;
#pragma unroll
            for (int w = 0; w < 8; w++) s2 += sRed[w][tid];
            g_rp[1][((size_t)(b * LL) + tj * 32 + tid) * NT + ti] = s2;
        }
    }
}

// ---------------------------------------------------------------------------
// One proximal step, 2 batches per block (one pair x batches b0, b0+1).
// Pair-packed u16 state, q-domain arithmetic. Per-block deterministic
// recompute of c (and Lm_t) for 128 rows by 128 threads.
template <bool FIRST>
__global__ __launch_bounds__(256, 5) void step2_k(const float* __restrict__ w_p,
                                                  int t) {
    const int  p  = blockIdx.x;
    const uchar2 pr = g_pairs[p];
    const int ti = pr.x, tj = pr.y;
    const int  b0   = blockIdx.y * 2;
    const bool diag = (ti == tj);
    const int  tid  = threadIdx.x;
    const int  r    = tid >> 3, g = tid & 7, c0 = g * 4;
    const int  warp = tid >> 5, lane = tid & 31;

    __shared__ float sRed[2][8][32];
    __shared__ float sC[128];   // [batch*64 + (ti rows 0..31 | tj rows 32..63)]

    const unsigned long long pol = mk_pol();

    const size_t pb0   = (size_t)(b0 * NPAIRS + p);
    const size_t pb1   = pb0 + NPAIRS;
    const size_t sidx0 = pb0 * 256 + r * 8 + g;
    const size_t sidx1 = pb1 * 256 + r * 8 + g;

    // Issue all independent loads up-front (6 LDGs -> high MLP).
    const uint4 sq0 = ld_u4_el(g_S + sidx0, pol);
    const uint4 sq1 = ld_u4_el(g_S + sidx1, pol);
    const uint2 up0 = ld_u2_el(g_Uh + pb0 * 1024 + r * 32 + c0, pol);
    const uint2 up1 = ld_u2_el(g_Uh + pb1 * 1024 + r * 32 + c0, pol);
    const uint4 rp4 = *(const uint4*)(g_RhoPp + p * 1024 + r * 32 + c0);
    const unsigned mw0 = g_Mbits[((size_t)(b0 * LL) + ti * 32 + r) * NT + tj];
    const unsigned mw1 = g_Mbits[((size_t)((b0 + 1) * LL) + ti * 32 + r) * NT + tj];

    const float at  = g_at[t];
    const float atq = at * QSCALE;

    // --- per-row c (and Lm_t): 4 warps, one row per thread, deterministic ---
    if (tid < 128) {
        const int batch = tid >> 6;
        const int idx   = tid & 63;
        const int b     = b0 + batch;
        const int rowl  = (idx < 32) ? (ti * 32 + idx) : (tj * 32 + (idx - 32));
        const float* rpr = g_rp[(t + 1) & 1] + ((size_t)(b * LL) + rowl) * NT;
        const float4 p0 = *(const float4*)(rpr + 0);
        const float4 p1 = *(const float4*)(rpr + 4);
        const float4 p2 = *(const float4*)(rpr + 8);
        const float4 p3 = *(const float4*)(rpr + 12);
        const float v = (((p0.x + p0.y) + (p0.z + p0.w)) +
                         ((p1.x + p1.y) + (p1.z + p1.w))) +
                        (((p2.x + p2.y) + (p2.z + p2.w)) +
                         ((p3.x + p3.y) + (p3.z + p3.w)));
        const float rd   = v - 1.0f;
        const float rpos = fmaxf(rd, 0.f);
        float lm;
        if (FIRST) lm = (*w_p) * rpos;
        else       lm = g_Lm[(t + 1) & 1][b * LL + rowl] + g_bt[t - 1] * rpos;
        const float sg = (rd > 0.f) ? 1.f : ((rd < 0.f) ? -1.f : 0.f);
        sC[tid] = lm * sg;
        if (diag && idx < 32) g_Lm[t & 1][b * LL + rowl] = lm;
    }

    // Shared thresholds (identical for both batches): rho * at, q-domain.
    const __half2* rh = (const __half2*)&rp4;
    float thx[4], thy[4];
#pragma unroll
    for (int k = 0; k < 4; k++) {
        const float2 rk = __half22float2(rh[k]);
        thx[k] = rk.x * atq;
        thy[k] = rk.y * atq;
    }
    __syncthreads();

    constexpr float HQ = 0.5f * QINV;

#pragma unroll
    for (int bb = 0; bb < 2; bb++) {
        const uint4    sq = bb ? sq1 : sq0;
        const uint2    up = bb ? up1 : up0;
        const unsigned mw = bb ? mw1 : mw0;
        const float*   cb = sC + bb * 64;
        const float    ci = cb[r];
        const float4  cj4 = *(const float4*)(cb + 32 + c0);
        const float   cjv[4] = {cj4.x, cj4.y, cj4.z, cj4.w};
        const unsigned sqs[4] = {sq.x, sq.y, sq.z, sq.w};
        const float2 u01 = __half22float2(*(const __half2*)&up.x);
        const float2 u23 = __half22float2(*(const __half2*)&up.y);
        const float uv[4] = {u01.x, u01.y, u23.x, u23.y};

        float pvq[4], tvq[4], a2q[4];
#pragma unroll
        for (int k = 0; k < 4; k++) {
            const bool  mk   = (mw >> (c0 + k)) & 1u;
            const float du   = uv[k] - (ci + cjv[k]);
            const float mult = mk ? fmaf(at, du, 1.f) : 1.f;
            const float spq  = (float)(sqs[k] & 0xffffu);
            const float stq  = (float)(sqs[k] >> 16);
            const float pv = fminf(fmaxf(fabsf(spq * mult) - thx[k], 0.f), QSCALE);
            const float tv = fminf(fmaxf(fabsf(stq * mult) - thy[k], 0.f), QSCALE);
            pvq[k] = pv; tvq[k] = tv;
            a2q[k] = mk ? (pv + tv) : 0.f;
        }

        st_u4_el(g_S + (bb ? sidx1 : sidx0),
                 make_uint4(qpackq(pvq[0], tvq[0]), qpackq(pvq[1], tvq[1]),
                            qpackq(pvq[2], tvq[2]), qpackq(pvq[3], tvq[3])), pol);

        // Row partials of A2, ti rows.
        float v = (a2q[0] + a2q[1]) + (a2q[2] + a2q[3]);
        v += __shfl_down_sync(0xffffffffu, v, 4, 8);
        v += __shfl_down_sync(0xffffffffu, v, 2, 8);
        v += __shfl_down_sync(0xffffffffu, v, 1, 8);
        if (g == 0)
            g_rp[t & 1][((size_t)((b0 + bb) * LL) + ti * 32 + r) * NT + tj] = v * HQ;
        // tj rows (off-diag only; diagonal would double count).
        if (!diag) {
#pragma unroll
            for (int k = 0; k < 4; k++) {
                float w2 = a2q[k];
                w2 += __shfl_xor_sync(0xffffffffu, w2, 16);
                w2 += __shfl_xor_sync(0xffffffffu, w2, 8);
                if (lane < 8) sRed[bb][warp][c0 + k] = w2;
            }
        }
    }

    if (!diag) {
        __syncthreads();
        if (tid < 64) {
            const int bb = tid >> 5, col = tid & 31;
            float s2 = 0.f;
#pragma unroll
            for (int w = 0; w < 8; w++) s2 += sRed[bb][w][col];
            g_rp[t & 1][((size_t)((b0 + bb) * LL) + tj * 32 + col) * NT + ti] = s2 * HQ;
        }
    }
}

// ---------------------------------------------------------------------------
// Last proximal step: computes A2 and writes dense output only.
__global__ __launch_bounds__(256, 7) void stepL_k(int t, float* __restrict__ out) {
    const int  p  = blockIdx.x;
    const uchar2 pr = g_pairs[p];
    const int ti = pr.x, tj = pr.y;
    const int  b    = blockIdx.y;
    const bool diag = (ti == tj);
    const int  tid  = threadIdx.x;
    const int  r    = tid >> 3, g = tid & 7, c0 = g * 4;

    __shared__ float sStage[32][33];
    __shared__ float sC[64];

    const size_t rowI = (size_t)(b * LL) + ti * 32 + r;
    const unsigned long long pol = mk_pol();

    const size_t pbase = (size_t)(b * NPAIRS + p);
    const size_t sidx  = pbase * 256 + r * 8 + g;
    const uint4  sq  = ld_u4_el(g_S + sidx, pol);
    const uint2  up  = ld_u2_el(g_Uh + pbase * 1024 + r * 32 + c0, pol);
    const uint4  rp4 = *(const uint4*)(g_RhoPp + p * 1024 + r * 32 + c0);
    const unsigned mw = g_Mbits[rowI * NT + tj];

    const float at  = g_at[t];
    const float atq = at * QSCALE;

    if (tid < 64) {
        const int rowl = (tid < 32) ? (ti * 32 + tid) : (tj * 32 + (tid - 32));
        const float* rpr = g_rp[(t + 1) & 1] + ((size_t)(b * LL) + rowl) * NT;
        const float4 p0 = *(const float4*)(rpr + 0);
        const float4 p1 = *(const float4*)(rpr + 4);
        const float4 p2 = *(const float4*)(rpr + 8);
        const float4 p3 = *(const float4*)(rpr + 12);
        const float v = (((p0.x + p0.y) + (p0.z + p0.w)) +
                         ((p1.x + p1.y) + (p1.z + p1.w))) +
                        (((p2.x + p2.y) + (p2.z + p2.w)) +
                         ((p3.x + p3.y) + (p3.z + p3.w)));
        const float rd   = v - 1.0f;
        const float rpos = fmaxf(rd, 0.f);
        const float lm = g_Lm[(t + 1) & 1][b * LL + rowl] + g_bt[t - 1] * rpos;
        const float sg = (rd > 0.f) ? 1.f : ((rd < 0.f) ? -1.f : 0.f);
        sC[tid] = lm * sg;
    }
    __syncthreads();

    const float ci = sC[r];
    const float4 cj4 = *(const float4*)(sC + 32 + c0);
    const float cjv[4] = {cj4.x, cj4.y, cj4.z, cj4.w};
    const unsigned sqs[4] = {sq.x, sq.y, sq.z, sq.w};
    const __half2* rh = (const __half2*)&rp4;
    const float2 u01 = __half22float2(*(const __half2*)&up.x);
    const float2 u23 = __half22float2(*(const __half2*)&up.y);
    const float uv[4] = {u01.x, u01.y, u23.x, u23.y};

    constexpr float HQ = 0.5f * QINV;
    float a2[4];
#pragma unroll
    for (int k = 0; k < 4; k++) {
        const bool  mk   = (mw >> (c0 + k)) & 1u;
        const float du   = uv[k] - (ci + cjv[k]);
        const float mult = mk ? fmaf(at, du, 1.f) : 1.f;
        const float2 rk  = __half22float2(rh[k]);
        const float spq  = (float)(sqs[k] & 0xffffu);
        const float stq  = (float)(sqs[k] >> 16);
        const float pv = fminf(fmaxf(fabsf(spq * mult) - rk.x * atq, 0.f), QSCALE);
        const float tv = fminf(fmaxf(fabsf(stq * mult) - rk.y * atq, 0.f), QSCALE);
        a2[k] = mk ? (pv + tv) * HQ : 0.f;
        sStage[c0 + k][r] = a2[k];
    }

    const size_t baseI = rowI * LL + tj * 32 + c0;
    *(float4*)(out + baseI) = make_float4(a2[0], a2[1], a2[2], a2[3]);
    __syncthreads();
    if (!diag) {
        const size_t baseJ = ((size_t)(b * LL) + tj * 32 + r) * LL + ti * 32 + c0;
        *(float4*)(out + baseJ) = make_float4(sStage[r][c0 + 0], sStage[r][c0 + 1],
                                              sStage[r][c0 + 2], sStage[r][c0 + 3]);
    }
}

// ---------------------------------------------------------------------------
extern "C" void kernel_launch(void* const* d_in, const int* in_sizes, int n_in,
                              void* d_out, int out_size) {
    const float* scores  = (const float*)d_in[0];
    const float* M       = (const float*)d_in[1];
    const float* s_p     = (const float*)d_in[2];
    const float* w_p     = (const float*)d_in[3];
    const float* rho     = (const float*)d_in[4];
    const float* alpha_p = (const float*)d_in[5];
    const float* belt_p  = (const float*)d_in[6];
    const float* lra_p   = (const float*)d_in[7];
    const float* lrb_p   = (const float*)d_in[8];
    float* out = (float*)d_out;
    (void)in_sizes; (void)n_in; (void)out_size;

    coef_k<<<1, 256>>>(alpha_p, belt_p, lra_p, lrb_p);
    rhop_k<<<NPAIRS, 256>>>(rho);

    init_k<<<dim3(NPAIRS, BB), 256>>>(scores, M, s_p);

    dim3 grid2(NPAIRS, BB / 2);
    step2_k<true><<<grid2, 256>>>(w_p, 0);
    for (int t = 1; t < NSTEPS - 1; t++)
        step2_k<false><<<grid2, 256>>>(w_p, t);
    stepL_k<<<dim3(NPAIRS, BB), 256>>>(NSTEPS - 1, out);
}

// round 13
// speedup vs baseline: 2.2739x; 1.0032x over previous
#include <cuda_runtime.h>
#include <cuda_fp16.h>
#include <math.h>

#define BB 64
#define LL 512
#define NSTEPS 20
#define NT 16
#define NPAIRS 136

#define QSCALE 65535.0f
#define QINV   (1.0f / 65535.0f)

// Persistent device scratch (allocations are forbidden in kernel_launch).
// Pair-packed u16 state: for upper tile-pair p=(ti,tj), element (r,c) stores
// (A_hat[i,j], A_hat[j,i]) quantized to u16 in [0,1]. One uint4 = 4 elements.
__device__ uint4    g_S[(size_t)BB * NPAIRS * 256];     // 35.7 MB pair state (u16 pairs)
__device__ __half   g_Uh[(size_t)BB * NPAIRS * 1024];   // 17.8 MB fp16 Usym (pair layout)
__device__ __half2  g_RhoPp[NPAIRS * 1024];             // (rho[i,j], rho[j,i]) pair layout
__device__ unsigned g_Mbits[(size_t)BB * LL * NT];      // 2 MB mask bitmap
__device__ float    g_rp[2][(size_t)BB * LL * NT];      // double-buffered row partials
__device__ float    g_Lm[2][BB * LL];                   // double-buffered multipliers
__device__ float    g_at[NSTEPS];                       // alpha * lr_alpha^t
__device__ float    g_bt[NSTEPS];                       // belt  * lr_belt^t
__device__ uchar2   g_pairs[NPAIRS];                    // (ti, tj) per linear pair id

// ---------------------------------------------------------------------------
// L2 evict_last cache-policy helpers (pin reused state in L2).
__device__ __forceinline__ unsigned long long mk_pol() {
    unsigned long long p;
    asm("createpolicy.fractional.L2::evict_last.b64 %0, 1.0;" : "=l"(p));
    return p;
}
__device__ __forceinline__ uint4 ld_u4_el(const uint4* a, unsigned long long pol) {
    uint4 v;
    asm("ld.global.L2::cache_hint.v4.u32 {%0,%1,%2,%3}, [%4], %5;"
        : "=r"(v.x), "=r"(v.y), "=r"(v.z), "=r"(v.w)
        : "l"(a), "l"(pol));
    return v;
}
__device__ __forceinline__ void st_u4_el(uint4* a, uint4 v, unsigned long long pol) {
    asm volatile("st.global.L2::cache_hint.v4.u32 [%0], {%1,%2,%3,%4}, %5;"
                 :: "l"(a), "r"(v.x), "r"(v.y), "r"(v.z), "r"(v.w), "l"(pol)
                 : "memory");
}
__device__ __forceinline__ uint2 ld_u2_el(const __half* a, unsigned long long pol) {
    uint2 v;
    asm("ld.global.L2::cache_hint.v2.u32 {%0,%1}, [%2], %3;"
        : "=r"(v.x), "=r"(v.y) : "l"(a), "l"(pol));
    return v;
}

__device__ __forceinline__ unsigned qpack(float a, float b) {
    return __float2uint_rn(a * QSCALE) | (__float2uint_rn(b * QSCALE) << 16);
}
// Pack two q-domain values (already in [0,65535]) via PRMT.
__device__ __forceinline__ unsigned qpackq(float a, float b) {
    return __byte_perm(__float2uint_rn(a), __float2uint_rn(b), 0x5410);
}

// ---------------------------------------------------------------------------
// One-time: step coefficients + pair table.
__global__ void coef_k(const float* __restrict__ alpha_p,
                       const float* __restrict__ belt_p,
                       const float* __restrict__ lra_p,
                       const float* __restrict__ lrb_p) {
    const int t = threadIdx.x;
    if (t < NSTEPS) {
        g_at[t] = (*alpha_p) * powf(*lra_p, (float)t);
        g_bt[t] = (*belt_p)  * powf(*lrb_p, (float)t);
    }
    if (t < NPAIRS) {
        int p = t, a = 0;
        while (p >= NT - a) { p -= NT - a; a++; }
        g_pairs[t] = make_uchar2((unsigned char)a, (unsigned char)(a + p));
    }
}

// ---------------------------------------------------------------------------
// Packed rho in pair layout (static, once). One block per pair.
__global__ __launch_bounds__(256) void rhop_k(const float* __restrict__ rho) {
    const uchar2 pr = g_pairs[blockIdx.x];
    const int ti = pr.x, tj = pr.y;
    const int tid = threadIdx.x;
    const int r = tid >> 3, c0 = (tid & 7) * 4;
    const float4 nat = *(const float4*)(rho + (ti * 32 + r) * LL + tj * 32 + c0);
    const float natv[4] = {nat.x, nat.y, nat.z, nat.w};
#pragma unroll
    for (int k = 0; k < 4; k++) {
        const float tr = rho[(tj * 32 + c0 + k) * LL + ti * 32 + r];
        g_RhoPp[blockIdx.x * 1024 + r * 32 + c0 + k] = __floats2half2_rn(natv[k], tr);
    }
}

// ---------------------------------------------------------------------------
// Init: pair-packed u16 state S0 = (scores[i,j], scores[j,i]), Usym (fp16,
// pair layout), mask bitmap, and row-partials of A0 = sym(scores)*M.
__global__ __launch_bounds__(256) void init_k(const float* __restrict__ scores,
                                              const float* __restrict__ M,
                                              const float* __restrict__ s_p) {
    const int  p  = blockIdx.x;
    const uchar2 pr = g_pairs[p];
    const int ti = pr.x, tj = pr.y;
    const int  b    = blockIdx.y;
    const bool diag = (ti == tj);
    const int  tid  = threadIdx.x;
    const int  r    = tid >> 3, g = tid & 7, c0 = g * 4;
    const int  warp = tid >> 5, lane = tid & 31;

    __shared__ float sS[32][33];
    __shared__ float sRed[8][32];

    const size_t rowI  = (size_t)(b * LL) + ti * 32 + r;
    const size_t rowJ  = (size_t)(b * LL) + tj * 32 + r;
    const size_t baseI = rowI * LL + tj * 32 + c0;
    const size_t baseJ = rowJ * LL + ti * 32 + c0;

    const float4 scI = *(const float4*)(scores + baseI);
    const float4 scJ = diag ? scI : *(const float4*)(scores + baseJ);
    const float4 mI4 = *(const float4*)(M + baseI);

    sS[r][c0 + 0] = scJ.x; sS[r][c0 + 1] = scJ.y;
    sS[r][c0 + 2] = scJ.z; sS[r][c0 + 3] = scJ.w;

    // Pack mask bits (M is exactly 0.0/1.0).
    unsigned wI = (((mI4.x > 0.5f) ? 1u : 0u) | ((mI4.y > 0.5f) ? 2u : 0u) |
                   ((mI4.z > 0.5f) ? 4u : 0u) | ((mI4.w > 0.5f) ? 8u : 0u)) << c0;
    wI |= __shfl_xor_sync(0xffffffffu, wI, 1, 8);
    wI |= __shfl_xor_sync(0xffffffffu, wI, 2, 8);
    wI |= __shfl_xor_sync(0xffffffffu, wI, 4, 8);
    if (g == 0) g_Mbits[rowI * NT + tj] = wI;
    if (!diag) {
        const float4 mJ4 = *(const float4*)(M + baseJ);
        unsigned wJ = (((mJ4.x > 0.5f) ? 1u : 0u) | ((mJ4.y > 0.5f) ? 2u : 0u) |
                       ((mJ4.z > 0.5f) ? 4u : 0u) | ((mJ4.w > 0.5f) ? 8u : 0u)) << c0;
        wJ |= __shfl_xor_sync(0xffffffffu, wJ, 1, 8);
        wJ |= __shfl_xor_sync(0xffffffffu, wJ, 2, 8);
        wJ |= __shfl_xor_sync(0xffffffffu, wJ, 4, 8);
        if (g == 0) g_Mbits[rowJ * NT + ti] = wJ;
    }

    const float sv = *s_p;
    __syncthreads();

    const float scIv[4] = {scI.x, scI.y, scI.z, scI.w};
    const float mIv[4]  = {mI4.x, mI4.y, mI4.z, mI4.w};
    float a2v[4], uu[4], trv[4];
#pragma unroll
    for (int k = 0; k < 4; k++) {
        trv[k] = sS[c0 + k][r];                 // scores[j, i]
        const float avg = 0.5f * (scIv[k] + trv[k]);
        uu[k]  = avg - sv;
        a2v[k] = avg * mIv[k];                  // exact fp32 A0 values
    }
    const size_t pbase = (size_t)(b * NPAIRS + p);
    // Pair-packed quantized S0
    g_S[pbase * 256 + r * 8 + g] =
        make_uint4(qpack(scIv[0], trv[0]), qpack(scIv[1], trv[1]),
                   qpack(scIv[2], trv[2]), qpack(scIv[3], trv[3]));
    // Usym fp16, pair layout
    {
        __half2 h01 = __floats2half2_rn(uu[0], uu[1]);
        __half2 h23 = __floats2half2_rn(uu[2], uu[3]);
        uint2 pk; pk.x = *(unsigned*)&h01; pk.y = *(unsigned*)&h23;
        *(uint2*)(g_Uh + pbase * 1024 + r * 32 + c0) = pk;
    }

    // Row partials of A0 (buffer 1: step 0 reads (0+1)&1 = 1).
    {
        float v = (a2v[0] + a2v[1]) + (a2v[2] + a2v[3]);
        v += __shfl_down_sync(0xffffffffu, v, 4, 8);
        v += __shfl_down_sync(0xffffffffu, v, 2, 8);
        v += __shfl_down_sync(0xffffffffu, v, 1, 8);
        if (g == 0) g_rp[1][rowI * NT + tj] = v;
    }
    if (!diag) {
#pragma unroll
        for (int k = 0; k < 4; k++) {
            float v = a2v[k];
            v += __shfl_xor_sync(0xffffffffu, v, 16);
            v += __shfl_xor_sync(0xffffffffu, v, 8);
            if (lane < 8) sRed[warp][c0 + k] = v;
        }
        __syncthreads();
        if (tid < 32) {
            float s2 = 0.f;
#pragma unroll
            for (int w = 0; w < 8; w++) s2 += sRed[w][tid];
            g_rp[1][((size_t)(b * LL) + tj * 32 + tid) * NT + ti] = s2;
        }
    }
}

// ---------------------------------------------------------------------------
// One proximal step, 2 batches per block (one pair x batches b0, b0+1).
// Pair-packed u16 state, q-domain arithmetic. Per-block deterministic
// recompute of c (and Lm_t) for 128 rows by 128 threads.
template <bool FIRST>
__global__ __launch_bounds__(256, 6) void step2_k(const float* __restrict__ w_p,
                                                  int t) {
    const int  p  = blockIdx.x;
    const uchar2 pr = g_pairs[p];
    const int ti = pr.x, tj = pr.y;
    const int  b0   = blockIdx.y * 2;
    const bool diag = (ti == tj);
    const int  tid  = threadIdx.x;
    const int  r    = tid >> 3, g = tid & 7, c0 = g * 4;
    const int  warp = tid >> 5, lane = tid & 31;

    __shared__ float sRed[2][8][32];
    __shared__ float sC[128];   // [batch*64 + (ti rows 0..31 | tj rows 32..63)]

    const unsigned long long pol = mk_pol();

    const size_t pb0   = (size_t)(b0 * NPAIRS + p);
    const size_t pb1   = pb0 + NPAIRS;
    const size_t sidx0 = pb0 * 256 + r * 8 + g;
    const size_t sidx1 = pb1 * 256 + r * 8 + g;

    // Hoist the long-latency loads (state + Usym) for MLP.
    const uint4 sq0 = ld_u4_el(g_S + sidx0, pol);
    const uint4 sq1 = ld_u4_el(g_S + sidx1, pol);
    const uint2 up0 = ld_u2_el(g_Uh + pb0 * 1024 + r * 32 + c0, pol);
    const uint2 up1 = ld_u2_el(g_Uh + pb1 * 1024 + r * 32 + c0, pol);

    const float at  = g_at[t];
    const float atq = at * QSCALE;

    // Shared thresholds (identical for both batches): rho * at, q-domain.
    float thx[4], thy[4];
    {
        const uint4 rp4 = *(const uint4*)(g_RhoPp + p * 1024 + r * 32 + c0);
        const __half2* rh = (const __half2*)&rp4;
#pragma unroll
        for (int k = 0; k < 4; k++) {
            const float2 rk = __half22float2(rh[k]);
            thx[k] = rk.x * atq;
            thy[k] = rk.y * atq;
        }
    }

    // --- per-row c (and Lm_t): 4 warps, one row per thread, deterministic ---
    if (tid < 128) {
        const int batch = tid >> 6;
        const int idx   = tid & 63;
        const int b     = b0 + batch;
        const int rowl  = (idx < 32) ? (ti * 32 + idx) : (tj * 32 + (idx - 32));
        const float* rpr = g_rp[(t + 1) & 1] + ((size_t)(b * LL) + rowl) * NT;
        const float4 p0 = *(const float4*)(rpr + 0);
        const float4 p1 = *(const float4*)(rpr + 4);
        const float4 p2 = *(const float4*)(rpr + 8);
        const float4 p3 = *(const float4*)(rpr + 12);
        const float v = (((p0.x + p0.y) + (p0.z + p0.w)) +
                         ((p1.x + p1.y) + (p1.z + p1.w))) +
                        (((p2.x + p2.y) + (p2.z + p2.w)) +
                         ((p3.x + p3.y) + (p3.z + p3.w)));
        const float rd   = v - 1.0f;
        const float rpos = fmaxf(rd, 0.f);
        float lm;
        if (FIRST) lm = (*w_p) * rpos;
        else       lm = g_Lm[(t + 1) & 1][b * LL + rowl] + g_bt[t - 1] * rpos;
        const float sg = (rd > 0.f) ? 1.f : ((rd < 0.f) ? -1.f : 0.f);
        sC[tid] = lm * sg;
        if (diag && idx < 32) g_Lm[t & 1][b * LL + rowl] = lm;
    }
    __syncthreads();

    constexpr float HQ = 0.5f * QINV;

#pragma unroll
    for (int bb = 0; bb < 2; bb++) {
        const uint4    sq = bb ? sq1 : sq0;
        const uint2    up = bb ? up1 : up0;
        const unsigned mw =
            g_Mbits[((size_t)((b0 + bb) * LL) + ti * 32 + r) * NT + tj];
        const float*   cb = sC + bb * 64;
        const float    ci = cb[r];
        const float4  cj4 = *(const float4*)(cb + 32 + c0);
        const float   cjv[4] = {cj4.x, cj4.y, cj4.z, cj4.w};
        const unsigned sqs[4] = {sq.x, sq.y, sq.z, sq.w};
        const float2 u01 = __half22float2(*(const __half2*)&up.x);
        const float2 u23 = __half22float2(*(const __half2*)&up.y);
        const float uv[4] = {u01.x, u01.y, u23.x, u23.y};

        uint4 outq;
        unsigned* oq = (unsigned*)&outq;
        float v = 0.f;       // row-partial accumulator (q units)
        float a2q[4];
#pragma unroll
        for (int k = 0; k < 4; k++) {
            const bool  mk   = (mw >> (c0 + k)) & 1u;
            const float du   = uv[k] - (ci + cjv[k]);
            const float mult = mk ? fmaf(at, du, 1.f) : 1.f;
            const float spq  = (float)(sqs[k] & 0xffffu);
            const float stq  = (float)(sqs[k] >> 16);
            const float pv = fminf(fmaxf(fabsf(spq * mult) - thx[k], 0.f), QSCALE);
            const float tv = fminf(fmaxf(fabsf(stq * mult) - thy[k], 0.f), QSCALE);
            oq[k]  = qpackq(pv, tv);
            a2q[k] = mk ? (pv + tv) : 0.f;
            v += a2q[k];
        }

        st_u4_el(g_S + (bb ? sidx1 : sidx0), outq, pol);

        // Row partials of A2, ti rows.
        v += __shfl_down_sync(0xffffffffu, v, 4, 8);
        v += __shfl_down_sync(0xffffffffu, v, 2, 8);
        v += __shfl_down_sync(0xffffffffu, v, 1, 8);
        if (g == 0)
            g_rp[t & 1][((size_t)((b0 + bb) * LL) + ti * 32 + r) * NT + tj] = v * HQ;
        // tj rows (off-diag only; diagonal would double count).
        if (!diag) {
#pragma unroll
            for (int k = 0; k < 4; k++) {
                float w2 = a2q[k];
                w2 += __shfl_xor_sync(0xffffffffu, w2, 16);
                w2 += __shfl_xor_sync(0xffffffffu, w2, 8);
                if (lane < 8) sRed[bb][warp][c0 + k] = w2;
            }
        }
    }

    if (!diag) {
        __syncthreads();
        if (tid < 64) {
            const int bb = tid >> 5, col = tid & 31;
            float s2 = 0.f;
#pragma unroll
            for (int w = 0; w < 8; w++) s2 += sRed[bb][w][col];
            g_rp[t & 1][((size_t)((b0 + bb) * LL) + tj * 32 + col) * NT + ti] = s2 * HQ;
        }
    }
}

// ---------------------------------------------------------------------------
// Last proximal step: computes A2 and writes dense output only.
__global__ __launch_bounds__(256, 7) void stepL_k(int t, float* __restrict__ out) {
    const int  p  = blockIdx.x;
    const uchar2 pr = g_pairs[p];
    const int ti = pr.x, tj = pr.y;
    const int  b    = blockIdx.y;
    const bool diag = (ti == tj);
    const int  tid  = threadIdx.x;
    const int  r    = tid >> 3, g = tid & 7, c0 = g * 4;

    __shared__ float sStage[32][33];
    __shared__ float sC[64];

    const size_t rowI = (size_t)(b * LL) + ti * 32 + r;
    const unsigned long long pol = mk_pol();

    const size_t pbase = (size_t)(b * NPAIRS + p);
    const size_t sidx  = pbase * 256 + r * 8 + g;
    const uint4  sq  = ld_u4_el(g_S + sidx, pol);
    const uint2  up  = ld_u2_el(g_Uh + pbase * 1024 + r * 32 + c0, pol);
    const uint4  rp4 = *(const uint4*)(g_RhoPp + p * 1024 + r * 32 + c0);
    const unsigned mw = g_Mbits[rowI * NT + tj];

    const float at  = g_at[t];
    const float atq = at * QSCALE;

    if (tid < 64) {
        const int rowl = (tid < 32) ? (ti * 32 + tid) : (tj * 32 + (tid - 32));
        const float* rpr = g_rp[(t + 1) & 1] + ((size_t)(b * LL) + rowl) * NT;
        const float4 p0 = *(const float4*)(rpr + 0);
        const float4 p1 = *(const float4*)(rpr + 4);
        const float4 p2 = *(const float4*)(rpr + 8);
        const float4 p3 = *(const float4*)(rpr + 12);
        const float v = (((p0.x + p0.y) + (p0.z + p0.w)) +
                         ((p1.x + p1.y) + (p1.z + p1.w))) +
                        (((p2.x + p2.y) + (p2.z + p2.w)) +
                         ((p3.x + p3.y) + (p3.z + p3.w)));
        const float rd   = v - 1.0f;
        const float rpos = fmaxf(rd, 0.f);
        const float lm = g_Lm[(t + 1) & 1][b * LL + rowl] + g_bt[t - 1] * rpos;
        const float sg = (rd > 0.f) ? 1.f : ((rd < 0.f) ? -1.f : 0.f);
        sC[tid] = lm * sg;
    }
    __syncthreads();

    const float ci = sC[r];
    const float4 cj4 = *(const float4*)(sC + 32 + c0);
    const float cjv[4] = {cj4.x, cj4.y, cj4.z, cj4.w};
    const unsigned sqs[4] = {sq.x, sq.y, sq.z, sq.w};
    const __half2* rh = (const __half2*)&rp4;
    const float2 u01 = __half22float2(*(const __half2*)&up.x);
    const float2 u23 = __half22float2(*(const __half2*)&up.y);
    const float uv[4] = {u01.x, u01.y, u23.x, u23.y};

    constexpr float HQ = 0.5f * QINV;
    float a2[4];
#pragma unroll
    for (int k = 0; k < 4; k++) {
        const bool  mk   = (mw >> (c0 + k)) & 1u;
        const float du   = uv[k] - (ci + cjv[k]);
        const float mult = mk ? fmaf(at, du, 1.f) : 1.f;
        const float2 rk  = __half22float2(rh[k]);
        const float spq  = (float)(sqs[k] & 0xffffu);
        const float stq  = (float)(sqs[k] >> 16);
        const float pv = fminf(fmaxf(fabsf(spq * mult) - rk.x * atq, 0.f), QSCALE);
        const float tv = fminf(fmaxf(fabsf(stq * mult) - rk.y * atq, 0.f), QSCALE);
        a2[k] = mk ? (pv + tv) * HQ : 0.f;
        sStage[c0 + k][r] = a2[k];
    }

    const size_t baseI = rowI * LL + tj * 32 + c0;
    *(float4*)(out + baseI) = make_float4(a2[0], a2[1], a2[2], a2[3]);
    __syncthreads();
    if (!diag) {
        const size_t baseJ = ((size_t)(b * LL) + tj * 32 + r) * LL + ti * 32 + c0;
        *(float4*)(out + baseJ) = make_float4(sStage[r][c0 + 0], sStage[r][c0 + 1],
                                              sStage[r][c0 + 2], sStage[r][c0 + 3]);
    }
}

// ---------------------------------------------------------------------------
extern "C" void kernel_launch(void* const* d_in, const int* in_sizes, int n_in,
                              void* d_out, int out_size) {
    const float* scores  = (const float*)d_in[0];
    const float* M       = (const float*)d_in[1];
    const float* s_p     = (const float*)d_in[2];
    const float* w_p     = (const float*)d_in[3];
    const float* rho     = (const float*)d_in[4];
    const float* alpha_p = (const float*)d_in[5];
    const float* belt_p  = (const float*)d_in[6];
    const float* lra_p   = (const float*)d_in[7];
    const float* lrb_p   = (const float*)d_in[8];
    float* out = (float*)d_out;
    (void)in_sizes; (void)n_in; (void)out_size;

    coef_k<<<1, 256>>>(alpha_p, belt_p, lra_p, lrb_p);
    rhop_k<<<NPAIRS, 256>>>(rho);

    init_k<<<dim3(NPAIRS, BB), 256>>>(scores, M, s_p);

    dim3 grid2(NPAIRS, BB / 2);
    step2_k<true><<<grid2, 256>>>(w_p, 0);
    for (int t = 1; t < NSTEPS - 1; t++)
        step2_k<false><<<grid2, 256>>>(w_p, t);
    stepL_k<<<dim3(NPAIRS, BB), 256>>>(NSTEPS - 1, out);
}